// round 13
// baseline (speedup 1.0000x reference)
#include <cuda_runtime.h>
#include <cstdint>

// ---------------- problem constants ----------------
#define Bq   16
#define Mq   2048
#define Kq   40
#define Nq   (Bq*Mq)      // 32768
#define INC  96
#define SDQ  4
#define PDQ  22
#define H1   128
#define CAND 128

typedef unsigned long long ull;

static const size_t ZOFF = (size_t)Nq * 96;        // floats before edge_index
static const size_t NKq  = (size_t)Nq * Kq;

// ---------------- device scratch ----------------
__device__ float g_s[Nq * SDQ];
__device__ float g_h[Nq * PDQ];
__device__ float g_aggr[Nq * 2 * PDQ];
__device__ float g_out[Nq * 96];
__device__ float g_t[Nq * H1];
__device__ float g_y[Nq * 96];
__device__ float g_c3[Bq * 96];
__device__ float g_part[Bq * 16 * 3 * 96];

__device__ __forceinline__ float fast_tanh(float v) {
    float e = __expf(2.f * v);
    return (e - 1.f) * __frcp_rn(e + 1.f);
}

// ---------------- packed f32x2 helpers (sm_103a) ----------------
__device__ __forceinline__ ull pack2(float a, float b) {
    ull r; asm("mov.b64 %0, {%1,%2};" : "=l"(r) : "f"(a), "f"(b)); return r;
}
__device__ __forceinline__ float2 unpack2(ull v) {
    float2 f; asm("mov.b64 {%0,%1}, %2;" : "=f"(f.x), "=f"(f.y) : "l"(v)); return f;
}
__device__ __forceinline__ ull fma2(ull a, ull b, ull c) {
    ull d; asm("fma.rn.f32x2 %0, %1, %2, %3;" : "=l"(d) : "l"(a), "l"(b), "l"(c)); return d;
}
__device__ __forceinline__ ull add2(ull a, ull b) {
    ull d; asm("add.rn.f32x2 %0, %1, %2;" : "=l"(d) : "l"(a), "l"(b)); return d;
}
__device__ __forceinline__ ull mul2(ull a, ull b) {
    ull d; asm("mul.rn.f32x2 %0, %1, %2;" : "=l"(d) : "l"(a), "l"(b)); return d;
}

// packed pair distance over NEGATED neighbor coords: per-element IEEE-rn ops
// in the SAME order as the scalar d2exact chain -> bit-identical results.
__device__ __forceinline__ ull d2pair(ull sqx2, ull sqy2, ull sqz2, ull sqw2,
                                      ull nx, ull ny, ull nz, ull nw) {
    ull px = add2(sqx2, nx), py = add2(sqy2, ny);
    ull pz = add2(sqz2, nz), pw = add2(sqw2, nw);
    return fma2(px, px, fma2(py, py, fma2(pz, pz, mul2(pw, pw))));
}

// ---- bitonic sort of NR*32 u64 keys, ascending (warp-collective) ----
template<int NR>
__device__ __forceinline__ void bitonic_sort(ull* v, int lane)
{
    #pragma unroll
    for (int kk = 2; kk <= NR * 32; kk <<= 1) {
        #pragma unroll
        for (int j = kk >> 1; j > 0; j >>= 1) {
            if (j >= 32) {
                int qx = j >> 5;
                #pragma unroll
                for (int q = 0; q < NR; q++) {
                    if ((q & qx) == 0) {
                        int e = q * 32 + lane;
                        bool up = ((e & kk) == 0);
                        ull a = v[q], b = v[q | qx];
                        bool sw2 = up ? (a > b) : (a < b);
                        if (sw2) { v[q] = b; v[q | qx] = a; }
                    }
                }
            } else {
                #pragma unroll
                for (int q = 0; q < NR; q++) {
                    int e = q * 32 + lane;
                    bool up = ((e & kk) == 0);
                    ull o = __shfl_xor_sync(0xffffffffu, v[q], j);
                    bool keepmin = (((lane & j) == 0) == up);
                    bool take = keepmin ? (o < v[q]) : (o > v[q]);
                    if (take) v[q] = o;
                }
            }
        }
    }
}

// ================= tiny no-op kernels (launch-slot padding for ncu) ======
__global__ void nop_k() {}

// ================= K0: s = x@W_s + b_s ; h = x@W_h + b_h =================
__global__ __launch_bounds__(256) void sh_kernel(
    const float* __restrict__ x,
    const float* __restrict__ Ws, const float* __restrict__ bs,
    const float* __restrict__ Wh, const float* __restrict__ bh)
{
    __shared__ float wsh[INC * 26];
    __shared__ float xs[32][INC];
    int tid = threadIdx.x;
    for (int idx = tid; idx < INC * 26; idx += 256) {
        int k = idx / 26, od = idx % 26;
        wsh[idx] = (od < SDQ) ? Ws[k * SDQ + od] : Wh[k * PDQ + (od - SDQ)];
    }
    const float* xb = x + (size_t)blockIdx.x * 32 * INC;
    for (int idx = tid; idx < 32 * INC / 4; idx += 256)
        ((float4*)xs)[idx] = ((const float4*)xb)[idx];
    __syncthreads();

    int w = tid >> 5, od = tid & 31;
    if (od < 26) {
        float bv = (od < SDQ) ? bs[od] : bh[od - SDQ];
        #pragma unroll
        for (int q = 0; q < 4; q++) {
            int nl = w * 4 + q;
            float acc = 0.f;
            #pragma unroll 8
            for (int k = 0; k < INC; k++) acc = fmaf(xs[nl][k], wsh[k * 26 + od], acc);
            int n = blockIdx.x * 32 + nl;
            if (od < SDQ) g_s[n * SDQ + od] = acc + bv;
            else          g_h[n * PDQ + (od - SDQ)] = acc + bv;
        }
    }
}

// ================= K1: kNN + weighted mean/max aggregation + edges =======
// Probes count in the PER-LANE word layout so the successful probe's accv is
// reused directly by compaction (no re-count phase).
__global__ __launch_bounds__(256, 3) void knn_kernel(float* __restrict__ dout)
{
    extern __shared__ float dsm[];
    float* nsx = dsm;                 // 2048 (negated coords)
    float* nsy = dsm + 2048;
    float* nsz = dsm + 4096;
    float* nsw = dsm + 6144;
    unsigned* d16 = (unsigned*)(dsm + 8192);          // 8 warps * 1024 u32 (32KB)
    ull* cand = (ull*)(dsm + 8192 + 8 * 1024);        // 8 * 128 u64 (8KB)

    int tid  = threadIdx.x;
    int lane = tid & 31;
    int w    = tid >> 5;
    int ev     = blockIdx.x >> 6;                // 64 blocks / event
    int qbase0 = (blockIdx.x & 63) * 32;

    const float4* sev = (const float4*)(g_s + (size_t)ev * Mq * SDQ);
    for (int j = tid; j < Mq; j += 256) {
        float4 s = sev[j];
        nsx[j] = -s.x; nsy[j] = -s.y; nsz[j] = -s.z; nsw[j] = -s.w;
    }
    __syncthreads();

    unsigned* myd16 = d16 + w * 1024;
    ull* mycand = cand + w * CAND;
    const float* hev = g_h + (size_t)ev * Mq * PDQ;
    int evM = ev * Mq;
    float Twarm = -1.f;

    for (int q = 0; q < 4; q++) {
        int qloc = qbase0 + w * 4 + q;
        int i = evM + qloc;
        float sqx = -nsx[qloc], sqy = -nsy[qloc], sqz = -nsz[qloc], sqw = -nsw[qloc];
        ull sqx2 = pack2(sqx, sqx), sqy2 = pack2(sqy, sqy);
        ull sqz2 = pack2(sqz, sqz), sqw2 = pack2(sqw, sqw);

        // ---- distance pass: packed f32x2, dual accumulators ----
        ull fsA = pack2(0.f, 0.f), fsB = pack2(0.f, 0.f);
        #pragma unroll 8
        for (int t = 0; t < 32; t += 2) {
            int p0 = lane + 32 * t;
            int p1 = p0 + 32;
            ull d2a = d2pair(sqx2, sqy2, sqz2, sqw2,
                             *(const ull*)&nsx[2 * p0], *(const ull*)&nsy[2 * p0],
                             *(const ull*)&nsz[2 * p0], *(const ull*)&nsw[2 * p0]);
            ull d2b = d2pair(sqx2, sqy2, sqz2, sqw2,
                             *(const ull*)&nsx[2 * p1], *(const ull*)&nsy[2 * p1],
                             *(const ull*)&nsz[2 * p1], *(const ull*)&nsw[2 * p1]);
            float2 da = unpack2(d2a), db = unpack2(d2b);
            myd16[p0] = (__float_as_uint(da.x) >> 16) | (__float_as_uint(da.y) & 0xffff0000u);
            myd16[p1] = (__float_as_uint(db.x) >> 16) | (__float_as_uint(db.y) & 0xffff0000u);
            fsA = add2(fsA, d2a);
            fsB = add2(fsB, d2b);
        }
        __syncwarp();

        // ---- threshold search in per-lane layout; accv reused later ----
        float T;
        float lo = 0.f, hi = 3.3e38f;
        if (Twarm > 0.f) {
            T = Twarm;
        } else {
            ull fs2 = add2(fsA, fsB);
            float2 fsp = unpack2(fs2);
            float fsum = fsp.x + fsp.y;
            #pragma unroll
            for (int o = 16; o; o >>= 1) fsum += __shfl_xor_sync(0xffffffffu, fsum, o);
            T = fsum * (0.20f / 2048.f);
        }
        unsigned T16 = 0u;
        unsigned accv = 0u;
        bool found = false;
        for (int it = 0; it < 16 && !found; ++it) {
            T16 = __float_as_uint(T) >> 16;
            unsigned TT = T16 * 0x10001u;
            accv = 0u;
            #pragma unroll
            for (int t = 0; t < 32; t++)
                accv = __vadd2(accv, __vsetleu2(myd16[lane + 32 * t], TT));
            int c = (int)((accv & 0xffffu) + (accv >> 16));
            c = __reduce_add_sync(0xffffffffu, c);
            if (c >= Kq && c <= 64) { found = true; break; }
            if (c < Kq) {
                lo = T;
                float Tm = T * sqrtf(50.f / fmaxf((float)c, 2.f));
                if (hi < 3e38f) {
                    float wdt = hi - lo;
                    Tm = fminf(fmaxf(Tm, lo + 0.25f * wdt), lo + 0.75f * wdt);
                } else {
                    Tm = fmaxf(Tm, T * 1.5f);
                }
                T = Tm;
            } else {
                hi = T;
                float Tm = T * sqrtf(50.f / (float)c);
                float wdt = hi - lo;
                Tm = fminf(fmaxf(Tm, lo + 0.25f * wdt), lo + 0.75f * wdt);
                T = Tm;
            }
        }
        if (!found) {   // exact bisection in u16 space (guaranteed >= Kq)
            unsigned l = 0u, h = 0x7f80u;
            for (int it = 0; it < 18 && !found; ++it) {
                unsigned mid = l + ((h - l) >> 1);
                unsigned TT = mid * 0x10001u;
                accv = 0u;
                #pragma unroll
                for (int t = 0; t < 32; t++)
                    accv = __vadd2(accv, __vsetleu2(myd16[lane + 32 * t], TT));
                int cc = (int)((accv & 0xffffu) + (accv >> 16));
                cc = __reduce_add_sync(0xffffffffu, cc);
                if (cc >= Kq && cc <= 64) { T16 = mid; found = true; }
                else if (cc >= Kq) h = mid;
                else l = mid;
                if (!found && h - l <= 1u) {
                    T16 = h; found = true;
                    unsigned TT2 = T16 * 0x10001u;
                    accv = 0u;
                    #pragma unroll
                    for (int t = 0; t < 32; t++)
                        accv = __vadd2(accv, __vsetleu2(myd16[lane + 32 * t], TT2));
                }
            }
        }
        Twarm = __uint_as_float((T16 << 16) | 0xffffu);

        // ---- compaction: scan accv -> sparse walk (no re-count) ----
        int cnt = (int)((accv & 0xffffu) + (accv >> 16));
        int incl = cnt;
        #pragma unroll
        for (int d = 1; d < 32; d <<= 1) {
            int n = __shfl_up_sync(0xffffffffu, incl, d);
            if (lane >= d) incl += n;
        }
        int pos = incl - cnt;                        // exclusive offset
        int C = __shfl_sync(0xffffffffu, incl, 31);  // total accepted
        if (C > CAND) C = CAND;

        #pragma unroll 4
        for (int t = 0; t < 32; t++) {
            unsigned u = myd16[lane + 32 * t];
            bool a0 = (u & 0xffffu) <= T16;
            bool a1 = (u >> 16) <= T16;
            if (a0 || a1) {
                int p = lane + 32 * t;
                ull nx = *(const ull*)&nsx[2 * p];
                ull ny = *(const ull*)&nsy[2 * p];
                ull nz = *(const ull*)&nsz[2 * p];
                ull nw = *(const ull*)&nsw[2 * p];
                ull d2p = d2pair(sqx2, sqy2, sqz2, sqw2, nx, ny, nz, nw);
                float2 dd = unpack2(d2p);
                if (a0) {
                    if (pos < CAND)
                        mycand[pos] = ((ull)__float_as_uint(dd.x) << 32) | (unsigned)(2 * p);
                    pos++;
                }
                if (a1) {
                    if (pos < CAND)
                        mycand[pos] = ((ull)__float_as_uint(dd.y) << 32) | (unsigned)(2 * p + 1);
                    pos++;
                }
            }
        }
        __syncwarp();

        // ---- sort: 64-key fast path, 128-key fallback ----
        ull v[4];
        if (C <= 64) {
            #pragma unroll
            for (int qq = 0; qq < 2; qq++) {
                int e = qq * 32 + lane;
                v[qq] = (e < C) ? mycand[e] : ~0ull;
            }
            bitonic_sort<2>(v, lane);
        } else {
            #pragma unroll
            for (int qq = 0; qq < 4; qq++) {
                int e = qq * 32 + lane;
                v[qq] = (e < C) ? mycand[e] : ~0ull;
            }
            bitonic_sort<4>(v, lane);
        }

        // ---- edge output (coalesced) ----
        float* esrc = dout + ZOFF + (size_t)i * Kq;
        float* etgt = esrc + NKq;
        esrc[lane] = (float)(evM + (int)(unsigned)(v[0] & 0xffffffffu));
        if (lane < 8)  esrc[32 + lane] = (float)(evM + (int)(unsigned)(v[1] & 0xffffffffu));
        if (lane < 10) *(float4*)&etgt[4 * lane] =
            make_float4((float)i, (float)i, (float)i, (float)i);

        // ---- top-40 broadcast aggregation (exact d2 from key) ----
        float meanAcc = 0.f;
        float maxAcc  = __int_as_float(0xff800000);
        #pragma unroll 8
        for (int r = 0; r < Kq; r++) {
            ull key = (r < 32) ? __shfl_sync(0xffffffffu, v[0], r)
                               : __shfl_sync(0xffffffffu, v[1], r - 32);
            float d2 = __uint_as_float((unsigned)(key >> 32));
            int j = (int)(unsigned)(key & 0xffffffffu);
            float wgt = __expf(-10.f * d2);
            if (lane < PDQ) {
                float msg = hev[(size_t)j * PDQ + lane] * wgt;
                meanAcc += msg;
                maxAcc = fmaxf(maxAcc, msg);
            }
        }
        if (lane < PDQ) {
            float* ag = g_aggr + (size_t)i * 2 * PDQ;
            ag[lane]       = meanAcc * (1.f / (float)Kq);
            ag[PDQ + lane] = maxAcc;
        }
        __syncwarp();
    }
}

// ================= row-tiled SIMT GEMM (R8 config: 8x8 f32x2, 2 CTAs) =====
template<int KD, int OC, int KCH, int NT, bool DOTANH, bool EVBIAS>
__global__ __launch_bounds__(NT, 2) void gemm_k(
    const float* __restrict__ A, const float* __restrict__ W,
    const float* __restrict__ bias, float* __restrict__ Cf)
{
    constexpr int RT = 128, AST = 132, CG = OC / 8;
    extern __shared__ float sm[];
    float* As  = sm;
    float* Wsm = sm + KCH * AST;
    int tid = threadIdx.x;
    int rowBase = blockIdx.x * RT;

    for (int idx = tid; idx < KD * OC / 4; idx += NT)
        ((float4*)Wsm)[idx] = ((const float4*)W)[idx];

    int cg = tid % CG, rg = tid / CG;
    int r0 = rg * 8, c0 = cg * 8;

    ull accp[4][8];
    {
        const float* bp = EVBIAS ? (bias + (rowBase >> 11) * 96) : bias;
        #pragma unroll
        for (int cc = 0; cc < 8; cc++) {
            ull bv = pack2(bp[c0 + cc], bp[c0 + cc]);
            #pragma unroll
            for (int rp = 0; rp < 4; rp++) accp[rp][cc] = bv;
        }
    }

    for (int kc = 0; kc < KD; kc += KCH) {
        __syncthreads();
        for (int idx = tid; idx < RT * KCH; idx += NT) {
            int r = idx / KCH, k = idx - r * KCH;
            As[k * AST + r] = A[(size_t)(rowBase + r) * KD + kc + k];
        }
        __syncthreads();
        #pragma unroll 8
        for (int k = 0; k < KCH; k++) {
            ulonglong2 a01 = *(const ulonglong2*)&As[k * AST + r0];
            ulonglong2 a23 = *(const ulonglong2*)&As[k * AST + r0 + 4];
            float4 w0 = *(const float4*)&Wsm[(kc + k) * OC + c0];
            float4 w1 = *(const float4*)&Wsm[(kc + k) * OC + c0 + 4];
            ull ap[4] = {a01.x, a01.y, a23.x, a23.y};
            ull wp[8] = {pack2(w0.x, w0.x), pack2(w0.y, w0.y),
                         pack2(w0.z, w0.z), pack2(w0.w, w0.w),
                         pack2(w1.x, w1.x), pack2(w1.y, w1.y),
                         pack2(w1.z, w1.z), pack2(w1.w, w1.w)};
            #pragma unroll
            for (int rp = 0; rp < 4; rp++)
                #pragma unroll
                for (int cc = 0; cc < 8; cc++)
                    accp[rp][cc] = fma2(ap[rp], wp[cc], accp[rp][cc]);
        }
    }

    #pragma unroll
    for (int rp = 0; rp < 4; rp++) {
        float vlo[8], vhi[8];
        #pragma unroll
        for (int cc = 0; cc < 8; cc++) {
            float2 f = unpack2(accp[rp][cc]);
            vlo[cc] = DOTANH ? fast_tanh(f.x) : f.x;
            vhi[cc] = DOTANH ? fast_tanh(f.y) : f.y;
        }
        size_t ro0 = (size_t)(rowBase + r0 + 2 * rp) * OC + c0;
        size_t ro1 = ro0 + OC;
        *(float4*)&Cf[ro0]     = make_float4(vlo[0], vlo[1], vlo[2], vlo[3]);
        *(float4*)&Cf[ro0 + 4] = make_float4(vlo[4], vlo[5], vlo[6], vlo[7]);
        *(float4*)&Cf[ro1]     = make_float4(vhi[0], vhi[1], vhi[2], vhi[3]);
        *(float4*)&Cf[ro1 + 4] = make_float4(vhi[4], vhi[5], vhi[6], vhi[7]);
    }
}

// ================= K2a: out = x@W_o1 + aggr@W_o2 + b_o2 (R8 config) =======
__global__ __launch_bounds__(192, 2) void gemm_out_k(
    const float* __restrict__ x, const float* __restrict__ aggr,
    const float* __restrict__ Wo1, const float* __restrict__ Wo2,
    const float* __restrict__ bias, float* __restrict__ outp)
{
    constexpr int RT = 128, AST = 132, NT = 192, OC = 96;
    extern __shared__ float sm[];
    float* As  = sm;                     // 48*132
    float* Ws1 = sm + 48 * AST;          // 96*96
    float* Ws2 = Ws1 + 96 * 96;          // 44*96
    int tid = threadIdx.x;
    int rowBase = blockIdx.x * RT;

    for (int idx = tid; idx < 96 * 96 / 4; idx += NT)
        ((float4*)Ws1)[idx] = ((const float4*)Wo1)[idx];
    for (int idx = tid; idx < 44 * 96 / 4; idx += NT)
        ((float4*)Ws2)[idx] = ((const float4*)Wo2)[idx];

    int cg = tid % 12, rg = tid / 12;
    int r0 = rg * 8, c0 = cg * 8;

    ull accp[4][8];
    #pragma unroll
    for (int cc = 0; cc < 8; cc++) {
        ull bv = pack2(bias[c0 + cc], bias[c0 + cc]);
        #pragma unroll
        for (int rp = 0; rp < 4; rp++) accp[rp][cc] = bv;
    }

    #pragma unroll
    for (int chunk = 0; chunk < 2; chunk++) {
        __syncthreads();
        for (int idx = tid; idx < RT * 48; idx += NT) {
            int r = idx / 48, k = idx - r * 48;
            As[k * AST + r] = x[(size_t)(rowBase + r) * 96 + chunk * 48 + k];
        }
        __syncthreads();
        #pragma unroll 8
        for (int k = 0; k < 48; k++) {
            ulonglong2 a01 = *(const ulonglong2*)&As[k * AST + r0];
            ulonglong2 a23 = *(const ulonglong2*)&As[k * AST + r0 + 4];
            float4 w0 = *(const float4*)&Ws1[(chunk * 48 + k) * OC + c0];
            float4 w1 = *(const float4*)&Ws1[(chunk * 48 + k) * OC + c0 + 4];
            ull ap[4] = {a01.x, a01.y, a23.x, a23.y};
            ull wp[8] = {pack2(w0.x, w0.x), pack2(w0.y, w0.y),
                         pack2(w0.z, w0.z), pack2(w0.w, w0.w),
                         pack2(w1.x, w1.x), pack2(w1.y, w1.y),
                         pack2(w1.z, w1.z), pack2(w1.w, w1.w)};
            #pragma unroll
            for (int rp = 0; rp < 4; rp++)
                #pragma unroll
                for (int cc = 0; cc < 8; cc++)
                    accp[rp][cc] = fma2(ap[rp], wp[cc], accp[rp][cc]);
        }
    }
    __syncthreads();
    for (int idx = tid; idx < RT * 44; idx += NT) {
        int r = idx / 44, k = idx - r * 44;
        As[k * AST + r] = aggr[(size_t)(rowBase + r) * 44 + k];
    }
    __syncthreads();
    #pragma unroll 4
    for (int k = 0; k < 44; k++) {
        ulonglong2 a01 = *(const ulonglong2*)&As[k * AST + r0];
        ulonglong2 a23 = *(const ulonglong2*)&As[k * AST + r0 + 4];
        float4 w0 = *(const float4*)&Ws2[k * OC + c0];
        float4 w1 = *(const float4*)&Ws2[k * OC + c0 + 4];
        ull ap[4] = {a01.x, a01.y, a23.x, a23.y};
        ull wp[8] = {pack2(w0.x, w0.x), pack2(w0.y, w0.y),
                     pack2(w0.z, w0.z), pack2(w0.w, w0.w),
                     pack2(w1.x, w1.x), pack2(w1.y, w1.y),
                     pack2(w1.z, w1.z), pack2(w1.w, w1.w)};
        #pragma unroll
        for (int rp = 0; rp < 4; rp++)
            #pragma unroll
            for (int cc = 0; cc < 8; cc++)
                accp[rp][cc] = fma2(ap[rp], wp[cc], accp[rp][cc]);
    }

    #pragma unroll
    for (int rp = 0; rp < 4; rp++) {
        float vlo[8], vhi[8];
        #pragma unroll
        for (int cc = 0; cc < 8; cc++) {
            float2 f = unpack2(accp[rp][cc]);
            vlo[cc] = f.x; vhi[cc] = f.y;
        }
        size_t ro0 = (size_t)(rowBase + r0 + 2 * rp) * OC + c0;
        size_t ro1 = ro0 + OC;
        *(float4*)&outp[ro0]     = make_float4(vlo[0], vlo[1], vlo[2], vlo[3]);
        *(float4*)&outp[ro0 + 4] = make_float4(vlo[4], vlo[5], vlo[6], vlo[7]);
        *(float4*)&outp[ro1]     = make_float4(vhi[0], vhi[1], vhi[2], vhi[3]);
        *(float4*)&outp[ro1 + 4] = make_float4(vhi[4], vhi[5], vhi[6], vhi[7]);
    }
}

// ================= K3a: per-(event,chunk) partial mean/min/max ===========
__global__ __launch_bounds__(192) void stats1_k()
{
    int ev = blockIdx.x >> 4, ch = blockIdx.x & 15;
    int tid = threadIdx.x;
    int d = tid % 96, half = tid / 96;
    __shared__ float red[3][192];

    const float* yb = g_y + (size_t)ev * Mq * 96 + (size_t)ch * 128 * 96;
    float sm = 0.f, mn = __int_as_float(0x7f800000), mx = __int_as_float(0xff800000);
    for (int r = half; r < 128; r += 2) {
        float v = yb[(size_t)r * 96 + d];
        sm += v; mn = fminf(mn, v); mx = fmaxf(mx, v);
    }
    red[0][tid] = sm; red[1][tid] = mn; red[2][tid] = mx;
    __syncthreads();
    if (tid < 96) {
        float* p = g_part + ((size_t)(ev * 16 + ch) * 3) * 96;
        p[tid]        = red[0][tid] + red[0][tid + 96];
        p[96 + tid]   = fminf(red[1][tid], red[1][tid + 96]);
        p[192 + tid]  = fmaxf(red[2][tid], red[2][tid + 96]);
    }
}

// ================= K3b: reduce partials + stats@W3[0:288]+b3 =============
__global__ __launch_bounds__(96) void stats2_k(
    const float* __restrict__ W3, const float* __restrict__ b3)
{
    int ev = blockIdx.x, tid = threadIdx.x;
    __shared__ float st[288];

    float sm = 0.f, mn = __int_as_float(0x7f800000), mx = __int_as_float(0xff800000);
    for (int ch = 0; ch < 16; ch++) {
        const float* p = g_part + ((size_t)(ev * 16 + ch) * 3) * 96;
        sm += p[tid];
        mn = fminf(mn, p[96 + tid]);
        mx = fmaxf(mx, p[192 + tid]);
    }
    st[tid]       = sm * (1.f / (float)Mq);
    st[96 + tid]  = mn;
    st[192 + tid] = mx;
    __syncthreads();

    float acc = b3[tid];
    #pragma unroll 4
    for (int k = 0; k < 288; k++) acc = fmaf(st[k], W3[(size_t)k * 96 + tid], acc);
    g_c3[ev * 96 + tid] = acc;
}

// ================= host launcher =========================================
extern "C" void kernel_launch(void* const* d_in, const int* in_sizes, int n_in,
                              void* d_out, int out_size)
{
    (void)out_size;
    static const int EXPECTED[15] = {
        3145728, 32768, 384, 4, 2112, 22, 9216, 4224, 96, 12288, 128, 12288, 96, 36864, 96
    };
    const void* P[15];
    bool ok = (n_in >= 15);
    if (ok) for (int i = 0; i < 15; i++) if (in_sizes[i] != EXPECTED[i]) { ok = false; break; }
    if (ok) {
        for (int i = 0; i < 15; i++) P[i] = d_in[i];
    } else {
        bool used[64] = {false};
        for (int r = 0; r < 15; r++) {
            P[r] = nullptr;
            for (int j = 0; j < n_in && j < 64; j++) {
                if (!used[j] && in_sizes[j] == EXPECTED[r]) { P[r] = d_in[j]; used[j] = true; break; }
            }
        }
    }

    const float* x   = (const float*)P[0];
    const float* Ws  = (const float*)P[2];
    const float* bs  = (const float*)P[3];
    const float* Wh  = (const float*)P[4];
    const float* bh  = (const float*)P[5];
    const float* Wo1 = (const float*)P[6];
    const float* Wo2 = (const float*)P[7];
    const float* bo2 = (const float*)P[8];
    const float* W1  = (const float*)P[9];
    const float* b1  = (const float*)P[10];
    const float* W2  = (const float*)P[11];
    const float* b2  = (const float*)P[12];
    const float* W3  = (const float*)P[13];
    const float* b3  = (const float*)P[14];
    float* dout = (float*)d_out;

    float *p_aggr, *p_out, *p_t, *p_y, *p_c3;
    cudaGetSymbolAddress((void**)&p_aggr, g_aggr);
    cudaGetSymbolAddress((void**)&p_out,  g_out);
    cudaGetSymbolAddress((void**)&p_t,    g_t);
    cudaGetSymbolAddress((void**)&p_y,    g_y);
    cudaGetSymbolAddress((void**)&p_c3,   g_c3);

    const int SMEM_KNN = 8192 * 4 + 8 * 1024 * 4 + 8 * CAND * 8;   // 73728
    const int SMEM_OUT = (48 * 132 + 96 * 96 + 44 * 96) * 4;       // 79104
    const int SMEM_B   = (96 * 132 + 96 * 128) * 4;                // 99840
    const int SMEM_C   = (64 * 132 + 128 * 96) * 4;                // 82944
    const int SMEM_Z   = (96 * 132 + 96 * 96) * 4;                 // 87552
    cudaFuncSetAttribute(knn_kernel, cudaFuncAttributeMaxDynamicSharedMemorySize, SMEM_KNN);
    cudaFuncSetAttribute(gemm_out_k, cudaFuncAttributeMaxDynamicSharedMemorySize, SMEM_OUT);
    cudaFuncSetAttribute(gemm_k<96, 128, 96, 256, true, false>,
                         cudaFuncAttributeMaxDynamicSharedMemorySize, SMEM_B);
    cudaFuncSetAttribute(gemm_k<128, 96, 64, 192, true, false>,
                         cudaFuncAttributeMaxDynamicSharedMemorySize, SMEM_C);
    cudaFuncSetAttribute(gemm_k<96, 96, 96, 192, true, true>,
                         cudaFuncAttributeMaxDynamicSharedMemorySize, SMEM_Z);

    sh_kernel<<<Nq / 32, 256>>>(x, Ws, bs, Wh, bh);
    nop_k<<<1, 32>>>();
    nop_k<<<1, 32>>>();
    // knn in the 4th launch slot (the one ncu captures)
    knn_kernel<<<Nq / 32, 256, SMEM_KNN>>>(dout);
    gemm_out_k<<<Nq / 128, 192, SMEM_OUT>>>(x, p_aggr, Wo1, Wo2, bo2, p_out);
    gemm_k<96, 128, 96, 256, true, false><<<Nq / 128, 256, SMEM_B>>>(p_out, W1, b1, p_t);
    gemm_k<128, 96, 64, 192, true, false><<<Nq / 128, 192, SMEM_C>>>(p_t, W2, b2, p_y);
    stats1_k<<<Bq * 16, 192>>>();
    stats2_k<<<Bq, 96>>>(W3, b3);
    gemm_k<96, 96, 96, 192, true, true><<<Nq / 128, 192, SMEM_Z>>>(p_y, W3 + 288 * 96, p_c3, dout);
}

// round 14
// speedup vs baseline: 1.5303x; 1.5303x over previous
#include <cuda_runtime.h>
#include <cstdint>

// ---------------- problem constants ----------------
#define Bq   16
#define Mq   2048
#define Kq   40
#define Nq   (Bq*Mq)      // 32768
#define INC  96
#define SDQ  4
#define PDQ  22
#define H1   128
#define CAND 128

typedef unsigned long long ull;

static const size_t ZOFF = (size_t)Nq * 96;        // floats before edge_index
static const size_t NKq  = (size_t)Nq * Kq;

// ---------------- device scratch ----------------
__device__ float g_s[Nq * SDQ];
__device__ float g_h[Nq * PDQ];
__device__ float g_aggr[Nq * 2 * PDQ];
__device__ float g_out[Nq * 96];
__device__ float g_t[Nq * H1];
__device__ float g_y[Nq * 96];
__device__ float g_c3[Bq * 96];
__device__ float g_part[Bq * 16 * 3 * 96];

__device__ __forceinline__ float fast_tanh(float v) {
    float e = __expf(2.f * v);
    return (e - 1.f) * __frcp_rn(e + 1.f);
}

// ---------------- packed f32x2 helpers (sm_103a) ----------------
__device__ __forceinline__ ull pack2(float a, float b) {
    ull r; asm("mov.b64 %0, {%1,%2};" : "=l"(r) : "f"(a), "f"(b)); return r;
}
__device__ __forceinline__ float2 unpack2(ull v) {
    float2 f; asm("mov.b64 {%0,%1}, %2;" : "=f"(f.x), "=f"(f.y) : "l"(v)); return f;
}
__device__ __forceinline__ ull fma2(ull a, ull b, ull c) {
    ull d; asm("fma.rn.f32x2 %0, %1, %2, %3;" : "=l"(d) : "l"(a), "l"(b), "l"(c)); return d;
}
__device__ __forceinline__ ull add2(ull a, ull b) {
    ull d; asm("add.rn.f32x2 %0, %1, %2;" : "=l"(d) : "l"(a), "l"(b)); return d;
}
__device__ __forceinline__ ull mul2(ull a, ull b) {
    ull d; asm("mul.rn.f32x2 %0, %1, %2;" : "=l"(d) : "l"(a), "l"(b)); return d;
}

// packed pair distance over NEGATED neighbor coords: per-element IEEE-rn ops
// in the SAME order as the scalar d2exact chain -> bit-identical results.
__device__ __forceinline__ ull d2pair(ull sqx2, ull sqy2, ull sqz2, ull sqw2,
                                      ull nx, ull ny, ull nz, ull nw) {
    ull px = add2(sqx2, nx), py = add2(sqy2, ny);
    ull pz = add2(sqz2, nz), pw = add2(sqw2, nw);
    return fma2(px, px, fma2(py, py, fma2(pz, pz, mul2(pw, pw))));
}

// ---- bitonic sort of NR*32 u64 keys, ascending (warp-collective) ----
template<int NR>
__device__ __forceinline__ void bitonic_sort(ull* v, int lane)
{
    #pragma unroll
    for (int kk = 2; kk <= NR * 32; kk <<= 1) {
        #pragma unroll
        for (int j = kk >> 1; j > 0; j >>= 1) {
            if (j >= 32) {
                int qx = j >> 5;
                #pragma unroll
                for (int q = 0; q < NR; q++) {
                    if ((q & qx) == 0) {
                        int e = q * 32 + lane;
                        bool up = ((e & kk) == 0);
                        ull a = v[q], b = v[q | qx];
                        bool sw2 = up ? (a > b) : (a < b);
                        if (sw2) { v[q] = b; v[q | qx] = a; }
                    }
                }
            } else {
                #pragma unroll
                for (int q = 0; q < NR; q++) {
                    int e = q * 32 + lane;
                    bool up = ((e & kk) == 0);
                    ull o = __shfl_xor_sync(0xffffffffu, v[q], j);
                    bool keepmin = (((lane & j) == 0) == up);
                    bool take = keepmin ? (o < v[q]) : (o > v[q]);
                    if (take) v[q] = o;
                }
            }
        }
    }
}

// ================= tiny no-op kernels (launch-slot padding for ncu) ======
__global__ void nop_k() {}

// ================= K0: s = x@W_s + b_s ; h = x@W_h + b_h =================
__global__ __launch_bounds__(256) void sh_kernel(
    const float* __restrict__ x,
    const float* __restrict__ Ws, const float* __restrict__ bs,
    const float* __restrict__ Wh, const float* __restrict__ bh)
{
    __shared__ float wsh[INC * 26];
    __shared__ float xs[32][INC];
    int tid = threadIdx.x;
    for (int idx = tid; idx < INC * 26; idx += 256) {
        int k = idx / 26, od = idx % 26;
        wsh[idx] = (od < SDQ) ? Ws[k * SDQ + od] : Wh[k * PDQ + (od - SDQ)];
    }
    const float* xb = x + (size_t)blockIdx.x * 32 * INC;
    for (int idx = tid; idx < 32 * INC / 4; idx += 256)
        ((float4*)xs)[idx] = ((const float4*)xb)[idx];
    __syncthreads();

    int w = tid >> 5, od = tid & 31;
    if (od < 26) {
        float bv = (od < SDQ) ? bs[od] : bh[od - SDQ];
        #pragma unroll
        for (int q = 0; q < 4; q++) {
            int nl = w * 4 + q;
            float acc = 0.f;
            #pragma unroll 8
            for (int k = 0; k < INC; k++) acc = fmaf(xs[nl][k], wsh[k * 26 + od], acc);
            int n = blockIdx.x * 32 + nl;
            if (od < SDQ) g_s[n * SDQ + od] = acc + bv;
            else          g_h[n * PDQ + (od - SDQ)] = acc + bv;
        }
    }
}

// ================= K1: kNN + weighted mean/max aggregation + edges =======
// R11 structure: f32x2 distance pass, vectorized uint4 probes, single scalar
// re-count, sort-64 fast path. fsum only computed for the first query.
__global__ __launch_bounds__(256, 3) void knn_kernel(float* __restrict__ dout)
{
    extern __shared__ float dsm[];
    float* nsx = dsm;                 // 2048 (negated coords)
    float* nsy = dsm + 2048;
    float* nsz = dsm + 4096;
    float* nsw = dsm + 6144;
    unsigned* d16 = (unsigned*)(dsm + 8192);          // 8 warps * 1024 u32 (32KB)
    ull* cand = (ull*)(dsm + 8192 + 8 * 1024);        // 8 * 128 u64 (8KB)

    int tid  = threadIdx.x;
    int lane = tid & 31;
    int w    = tid >> 5;
    int ev     = blockIdx.x >> 6;                // 64 blocks / event
    int qbase0 = (blockIdx.x & 63) * 32;

    const float4* sev = (const float4*)(g_s + (size_t)ev * Mq * SDQ);
    for (int j = tid; j < Mq; j += 256) {
        float4 s = sev[j];
        nsx[j] = -s.x; nsy[j] = -s.y; nsz[j] = -s.z; nsw[j] = -s.w;
    }
    __syncthreads();

    unsigned* myd16 = d16 + w * 1024;
    ull* mycand = cand + w * CAND;
    const uint4* dv16 = (const uint4*)myd16;
    const float* hev = g_h + (size_t)ev * Mq * PDQ;
    int evM = ev * Mq;
    float Twarm = -1.f;

    for (int q = 0; q < 4; q++) {
        int qloc = qbase0 + w * 4 + q;
        int i = evM + qloc;
        float sqx = -nsx[qloc], sqy = -nsy[qloc], sqz = -nsz[qloc], sqw = -nsw[qloc];
        ull sqx2 = pack2(sqx, sqx), sqy2 = pack2(sqy, sqy);
        ull sqz2 = pack2(sqz, sqz), sqw2 = pack2(sqw, sqw);

        // ---- distance pass: packed f32x2; fsum only for first query ----
        float T;
        if (Twarm > 0.f) {
            #pragma unroll 8
            for (int t = 0; t < 32; t++) {
                int p = lane + 32 * t;
                ull d2p = d2pair(sqx2, sqy2, sqz2, sqw2,
                                 *(const ull*)&nsx[2 * p], *(const ull*)&nsy[2 * p],
                                 *(const ull*)&nsz[2 * p], *(const ull*)&nsw[2 * p]);
                float2 dd = unpack2(d2p);
                myd16[p] = (__float_as_uint(dd.x) >> 16) | (__float_as_uint(dd.y) & 0xffff0000u);
            }
            T = Twarm;
        } else {
            ull fs2 = pack2(0.f, 0.f);
            #pragma unroll 8
            for (int t = 0; t < 32; t++) {
                int p = lane + 32 * t;
                ull d2p = d2pair(sqx2, sqy2, sqz2, sqw2,
                                 *(const ull*)&nsx[2 * p], *(const ull*)&nsy[2 * p],
                                 *(const ull*)&nsz[2 * p], *(const ull*)&nsw[2 * p]);
                float2 dd = unpack2(d2p);
                myd16[p] = (__float_as_uint(dd.x) >> 16) | (__float_as_uint(dd.y) & 0xffff0000u);
                fs2 = add2(fs2, d2p);
            }
            float2 fsp = unpack2(fs2);
            float fsum = fsp.x + fsp.y;
            #pragma unroll
            for (int o = 16; o; o >>= 1) fsum += __shfl_xor_sync(0xffffffffu, fsum, o);
            T = fsum * (0.20f / 2048.f);
        }
        __syncwarp();

        // ---- threshold search: vectorized probes; count in [Kq, 64] ----
        float lo = 0.f, hi = 3.3e38f;
        unsigned T16 = 0u;
        bool found = false;
        for (int it = 0; it < 16 && !found; ++it) {
            T16 = __float_as_uint(T) >> 16;
            unsigned TT = T16 * 0x10001u;
            unsigned acc = 0;
            #pragma unroll
            for (int t4 = 0; t4 < 8; t4++) {
                uint4 u = dv16[lane + 32 * t4];
                acc = __vadd2(acc, __vsetleu2(u.x, TT));
                acc = __vadd2(acc, __vsetleu2(u.y, TT));
                acc = __vadd2(acc, __vsetleu2(u.z, TT));
                acc = __vadd2(acc, __vsetleu2(u.w, TT));
            }
            int c = (int)((acc & 0xffffu) + (acc >> 16));
            c = __reduce_add_sync(0xffffffffu, c);
            if (c >= Kq && c <= 64) { found = true; break; }
            if (c < Kq) {
                lo = T;
                float Tm = T * sqrtf(50.f / fmaxf((float)c, 2.f));
                if (hi < 3e38f) {
                    float wdt = hi - lo;
                    Tm = fminf(fmaxf(Tm, lo + 0.25f * wdt), lo + 0.75f * wdt);
                } else {
                    Tm = fmaxf(Tm, T * 1.5f);
                }
                T = Tm;
            } else {
                hi = T;
                float Tm = T * sqrtf(50.f / (float)c);
                float wdt = hi - lo;
                Tm = fminf(fmaxf(Tm, lo + 0.25f * wdt), lo + 0.75f * wdt);
                T = Tm;
            }
        }
        if (!found) {   // exact bisection in u16 space (guaranteed >= Kq)
            unsigned l = 0u, h = 0x7f80u;
            for (int it = 0; it < 18 && !found; ++it) {
                unsigned mid = l + ((h - l) >> 1);
                unsigned TT = mid * 0x10001u;
                unsigned acc = 0;
                #pragma unroll
                for (int t4 = 0; t4 < 8; t4++) {
                    uint4 u = dv16[lane + 32 * t4];
                    acc = __vadd2(acc, __vsetleu2(u.x, TT));
                    acc = __vadd2(acc, __vsetleu2(u.y, TT));
                    acc = __vadd2(acc, __vsetleu2(u.z, TT));
                    acc = __vadd2(acc, __vsetleu2(u.w, TT));
                }
                int cc = (int)((acc & 0xffffu) + (acc >> 16));
                cc = __reduce_add_sync(0xffffffffu, cc);
                if (cc >= Kq && cc <= 64) { T16 = mid; found = true; }
                else if (cc >= Kq) h = mid;
                else l = mid;
                if (!found && h - l <= 1u) { T16 = h; found = true; }
            }
        }
        Twarm = __uint_as_float((T16 << 16) | 0xffffu);

        // ---- compaction: per-lane count -> warp scan -> sparse walk ----
        unsigned TT = T16 * 0x10001u;
        unsigned accv = 0u;
        #pragma unroll
        for (int t = 0; t < 32; t++)
            accv = __vadd2(accv, __vsetleu2(myd16[lane + 32 * t], TT));
        int cnt = (int)((accv & 0xffffu) + (accv >> 16));
        int incl = cnt;
        #pragma unroll
        for (int d = 1; d < 32; d <<= 1) {
            int n = __shfl_up_sync(0xffffffffu, incl, d);
            if (lane >= d) incl += n;
        }
        int pos = incl - cnt;                        // exclusive offset
        int C = __shfl_sync(0xffffffffu, incl, 31);  // total accepted
        if (C > CAND) C = CAND;

        #pragma unroll 4
        for (int t = 0; t < 32; t++) {
            unsigned u = myd16[lane + 32 * t];
            bool a0 = (u & 0xffffu) <= T16;
            bool a1 = (u >> 16) <= T16;
            if (a0 || a1) {
                int p = lane + 32 * t;
                ull d2p = d2pair(sqx2, sqy2, sqz2, sqw2,
                                 *(const ull*)&nsx[2 * p], *(const ull*)&nsy[2 * p],
                                 *(const ull*)&nsz[2 * p], *(const ull*)&nsw[2 * p]);
                float2 dd = unpack2(d2p);
                if (a0) {
                    if (pos < CAND)
                        mycand[pos] = ((ull)__float_as_uint(dd.x) << 32) | (unsigned)(2 * p);
                    pos++;
                }
                if (a1) {
                    if (pos < CAND)
                        mycand[pos] = ((ull)__float_as_uint(dd.y) << 32) | (unsigned)(2 * p + 1);
                    pos++;
                }
            }
        }
        __syncwarp();

        // ---- sort: 64-key fast path, 128-key fallback ----
        ull v[4];
        if (C <= 64) {
            #pragma unroll
            for (int qq = 0; qq < 2; qq++) {
                int e = qq * 32 + lane;
                v[qq] = (e < C) ? mycand[e] : ~0ull;
            }
            bitonic_sort<2>(v, lane);
        } else {
            #pragma unroll
            for (int qq = 0; qq < 4; qq++) {
                int e = qq * 32 + lane;
                v[qq] = (e < C) ? mycand[e] : ~0ull;
            }
            bitonic_sort<4>(v, lane);
        }

        // ---- edge output (coalesced) ----
        float* esrc = dout + ZOFF + (size_t)i * Kq;
        float* etgt = esrc + NKq;
        esrc[lane] = (float)(evM + (int)(unsigned)(v[0] & 0xffffffffu));
        if (lane < 8)  esrc[32 + lane] = (float)(evM + (int)(unsigned)(v[1] & 0xffffffffu));
        if (lane < 10) *(float4*)&etgt[4 * lane] =
            make_float4((float)i, (float)i, (float)i, (float)i);

        // ---- top-40 broadcast aggregation (exact d2 from key) ----
        float meanAcc = 0.f;
        float maxAcc  = __int_as_float(0xff800000);
        #pragma unroll 8
        for (int r = 0; r < Kq; r++) {
            ull key = (r < 32) ? __shfl_sync(0xffffffffu, v[0], r)
                               : __shfl_sync(0xffffffffu, v[1], r - 32);
            float d2 = __uint_as_float((unsigned)(key >> 32));
            int j = (int)(unsigned)(key & 0xffffffffu);
            float wgt = __expf(-10.f * d2);
            if (lane < PDQ) {
                float msg = hev[(size_t)j * PDQ + lane] * wgt;
                meanAcc += msg;
                maxAcc = fmaxf(maxAcc, msg);
            }
        }
        if (lane < PDQ) {
            float* ag = g_aggr + (size_t)i * 2 * PDQ;
            ag[lane]       = meanAcc * (1.f / (float)Kq);
            ag[PDQ + lane] = maxAcc;
        }
        __syncwarp();
    }
}

// ================= row-tiled SIMT GEMM (R8 config: 8x8 f32x2, 2 CTAs) =====
template<int KD, int OC, int KCH, int NT, bool DOTANH, bool EVBIAS>
__global__ __launch_bounds__(NT, 2) void gemm_k(
    const float* __restrict__ A, const float* __restrict__ W,
    const float* __restrict__ bias, float* __restrict__ Cf)
{
    constexpr int RT = 128, AST = 132, CG = OC / 8;
    extern __shared__ float sm[];
    float* As  = sm;
    float* Wsm = sm + KCH * AST;
    int tid = threadIdx.x;
    int rowBase = blockIdx.x * RT;

    for (int idx = tid; idx < KD * OC / 4; idx += NT)
        ((float4*)Wsm)[idx] = ((const float4*)W)[idx];

    int cg = tid % CG, rg = tid / CG;
    int r0 = rg * 8, c0 = cg * 8;

    ull accp[4][8];
    {
        const float* bp = EVBIAS ? (bias + (rowBase >> 11) * 96) : bias;
        #pragma unroll
        for (int cc = 0; cc < 8; cc++) {
            ull bv = pack2(bp[c0 + cc], bp[c0 + cc]);
            #pragma unroll
            for (int rp = 0; rp < 4; rp++) accp[rp][cc] = bv;
        }
    }

    for (int kc = 0; kc < KD; kc += KCH) {
        __syncthreads();
        for (int idx = tid; idx < RT * KCH; idx += NT) {
            int r = idx / KCH, k = idx - r * KCH;
            As[k * AST + r] = A[(size_t)(rowBase + r) * KD + kc + k];
        }
        __syncthreads();
        #pragma unroll 8
        for (int k = 0; k < KCH; k++) {
            ulonglong2 a01 = *(const ulonglong2*)&As[k * AST + r0];
            ulonglong2 a23 = *(const ulonglong2*)&As[k * AST + r0 + 4];
            float4 w0 = *(const float4*)&Wsm[(kc + k) * OC + c0];
            float4 w1 = *(const float4*)&Wsm[(kc + k) * OC + c0 + 4];
            ull ap[4] = {a01.x, a01.y, a23.x, a23.y};
            ull wp[8] = {pack2(w0.x, w0.x), pack2(w0.y, w0.y),
                         pack2(w0.z, w0.z), pack2(w0.w, w0.w),
                         pack2(w1.x, w1.x), pack2(w1.y, w1.y),
                         pack2(w1.z, w1.z), pack2(w1.w, w1.w)};
            #pragma unroll
            for (int rp = 0; rp < 4; rp++)
                #pragma unroll
                for (int cc = 0; cc < 8; cc++)
                    accp[rp][cc] = fma2(ap[rp], wp[cc], accp[rp][cc]);
        }
    }

    #pragma unroll
    for (int rp = 0; rp < 4; rp++) {
        float vlo[8], vhi[8];
        #pragma unroll
        for (int cc = 0; cc < 8; cc++) {
            float2 f = unpack2(accp[rp][cc]);
            vlo[cc] = DOTANH ? fast_tanh(f.x) : f.x;
            vhi[cc] = DOTANH ? fast_tanh(f.y) : f.y;
        }
        size_t ro0 = (size_t)(rowBase + r0 + 2 * rp) * OC + c0;
        size_t ro1 = ro0 + OC;
        *(float4*)&Cf[ro0]     = make_float4(vlo[0], vlo[1], vlo[2], vlo[3]);
        *(float4*)&Cf[ro0 + 4] = make_float4(vlo[4], vlo[5], vlo[6], vlo[7]);
        *(float4*)&Cf[ro1]     = make_float4(vhi[0], vhi[1], vhi[2], vhi[3]);
        *(float4*)&Cf[ro1 + 4] = make_float4(vhi[4], vhi[5], vhi[6], vhi[7]);
    }
}

// ================= K2a: out = x@W_o1 + aggr@W_o2 + b_o2 (R8 config) =======
__global__ __launch_bounds__(192, 2) void gemm_out_k(
    const float* __restrict__ x, const float* __restrict__ aggr,
    const float* __restrict__ Wo1, const float* __restrict__ Wo2,
    const float* __restrict__ bias, float* __restrict__ outp)
{
    constexpr int RT = 128, AST = 132, NT = 192, OC = 96;
    extern __shared__ float sm[];
    float* As  = sm;                     // 48*132
    float* Ws1 = sm + 48 * AST;          // 96*96
    float* Ws2 = Ws1 + 96 * 96;          // 44*96
    int tid = threadIdx.x;
    int rowBase = blockIdx.x * RT;

    for (int idx = tid; idx < 96 * 96 / 4; idx += NT)
        ((float4*)Ws1)[idx] = ((const float4*)Wo1)[idx];
    for (int idx = tid; idx < 44 * 96 / 4; idx += NT)
        ((float4*)Ws2)[idx] = ((const float4*)Wo2)[idx];

    int cg = tid % 12, rg = tid / 12;
    int r0 = rg * 8, c0 = cg * 8;

    ull accp[4][8];
    #pragma unroll
    for (int cc = 0; cc < 8; cc++) {
        ull bv = pack2(bias[c0 + cc], bias[c0 + cc]);
        #pragma unroll
        for (int rp = 0; rp < 4; rp++) accp[rp][cc] = bv;
    }

    #pragma unroll
    for (int chunk = 0; chunk < 2; chunk++) {
        __syncthreads();
        for (int idx = tid; idx < RT * 48; idx += NT) {
            int r = idx / 48, k = idx - r * 48;
            As[k * AST + r] = x[(size_t)(rowBase + r) * 96 + chunk * 48 + k];
        }
        __syncthreads();
        #pragma unroll 8
        for (int k = 0; k < 48; k++) {
            ulonglong2 a01 = *(const ulonglong2*)&As[k * AST + r0];
            ulonglong2 a23 = *(const ulonglong2*)&As[k * AST + r0 + 4];
            float4 w0 = *(const float4*)&Ws1[(chunk * 48 + k) * OC + c0];
            float4 w1 = *(const float4*)&Ws1[(chunk * 48 + k) * OC + c0 + 4];
            ull ap[4] = {a01.x, a01.y, a23.x, a23.y};
            ull wp[8] = {pack2(w0.x, w0.x), pack2(w0.y, w0.y),
                         pack2(w0.z, w0.z), pack2(w0.w, w0.w),
                         pack2(w1.x, w1.x), pack2(w1.y, w1.y),
                         pack2(w1.z, w1.z), pack2(w1.w, w1.w)};
            #pragma unroll
            for (int rp = 0; rp < 4; rp++)
                #pragma unroll
                for (int cc = 0; cc < 8; cc++)
                    accp[rp][cc] = fma2(ap[rp], wp[cc], accp[rp][cc]);
        }
    }
    __syncthreads();
    for (int idx = tid; idx < RT * 44; idx += NT) {
        int r = idx / 44, k = idx - r * 44;
        As[k * AST + r] = aggr[(size_t)(rowBase + r) * 44 + k];
    }
    __syncthreads();
    #pragma unroll 4
    for (int k = 0; k < 44; k++) {
        ulonglong2 a01 = *(const ulonglong2*)&As[k * AST + r0];
        ulonglong2 a23 = *(const ulonglong2*)&As[k * AST + r0 + 4];
        float4 w0 = *(const float4*)&Ws2[k * OC + c0];
        float4 w1 = *(const float4*)&Ws2[k * OC + c0 + 4];
        ull ap[4] = {a01.x, a01.y, a23.x, a23.y};
        ull wp[8] = {pack2(w0.x, w0.x), pack2(w0.y, w0.y),
                     pack2(w0.z, w0.z), pack2(w0.w, w0.w),
                     pack2(w1.x, w1.x), pack2(w1.y, w1.y),
                     pack2(w1.z, w1.z), pack2(w1.w, w1.w)};
        #pragma unroll
        for (int rp = 0; rp < 4; rp++)
            #pragma unroll
            for (int cc = 0; cc < 8; cc++)
                accp[rp][cc] = fma2(ap[rp], wp[cc], accp[rp][cc]);
    }

    #pragma unroll
    for (int rp = 0; rp < 4; rp++) {
        float vlo[8], vhi[8];
        #pragma unroll
        for (int cc = 0; cc < 8; cc++) {
            float2 f = unpack2(accp[rp][cc]);
            vlo[cc] = f.x; vhi[cc] = f.y;
        }
        size_t ro0 = (size_t)(rowBase + r0 + 2 * rp) * OC + c0;
        size_t ro1 = ro0 + OC;
        *(float4*)&outp[ro0]     = make_float4(vlo[0], vlo[1], vlo[2], vlo[3]);
        *(float4*)&outp[ro0 + 4] = make_float4(vlo[4], vlo[5], vlo[6], vlo[7]);
        *(float4*)&outp[ro1]     = make_float4(vhi[0], vhi[1], vhi[2], vhi[3]);
        *(float4*)&outp[ro1 + 4] = make_float4(vhi[4], vhi[5], vhi[6], vhi[7]);
    }
}

// ================= K3a: per-(event,chunk) partial mean/min/max ===========
__global__ __launch_bounds__(192) void stats1_k()
{
    int ev = blockIdx.x >> 4, ch = blockIdx.x & 15;
    int tid = threadIdx.x;
    int d = tid % 96, half = tid / 96;
    __shared__ float red[3][192];

    const float* yb = g_y + (size_t)ev * Mq * 96 + (size_t)ch * 128 * 96;
    float sm = 0.f, mn = __int_as_float(0x7f800000), mx = __int_as_float(0xff800000);
    for (int r = half; r < 128; r += 2) {
        float v = yb[(size_t)r * 96 + d];
        sm += v; mn = fminf(mn, v); mx = fmaxf(mx, v);
    }
    red[0][tid] = sm; red[1][tid] = mn; red[2][tid] = mx;
    __syncthreads();
    if (tid < 96) {
        float* p = g_part + ((size_t)(ev * 16 + ch) * 3) * 96;
        p[tid]        = red[0][tid] + red[0][tid + 96];
        p[96 + tid]   = fminf(red[1][tid], red[1][tid + 96]);
        p[192 + tid]  = fmaxf(red[2][tid], red[2][tid + 96]);
    }
}

// ================= K3b: reduce partials + stats@W3[0:288]+b3 =============
__global__ __launch_bounds__(96) void stats2_k(
    const float* __restrict__ W3, const float* __restrict__ b3)
{
    int ev = blockIdx.x, tid = threadIdx.x;
    __shared__ float st[288];

    float sm = 0.f, mn = __int_as_float(0x7f800000), mx = __int_as_float(0xff800000);
    for (int ch = 0; ch < 16; ch++) {
        const float* p = g_part + ((size_t)(ev * 16 + ch) * 3) * 96;
        sm += p[tid];
        mn = fminf(mn, p[96 + tid]);
        mx = fmaxf(mx, p[192 + tid]);
    }
    st[tid]       = sm * (1.f / (float)Mq);
    st[96 + tid]  = mn;
    st[192 + tid] = mx;
    __syncthreads();

    float acc = b3[tid];
    #pragma unroll 4
    for (int k = 0; k < 288; k++) acc = fmaf(st[k], W3[(size_t)k * 96 + tid], acc);
    g_c3[ev * 96 + tid] = acc;
}

// ================= host launcher =========================================
extern "C" void kernel_launch(void* const* d_in, const int* in_sizes, int n_in,
                              void* d_out, int out_size)
{
    (void)out_size;
    static const int EXPECTED[15] = {
        3145728, 32768, 384, 4, 2112, 22, 9216, 4224, 96, 12288, 128, 12288, 96, 36864, 96
    };
    const void* P[15];
    bool ok = (n_in >= 15);
    if (ok) for (int i = 0; i < 15; i++) if (in_sizes[i] != EXPECTED[i]) { ok = false; break; }
    if (ok) {
        for (int i = 0; i < 15; i++) P[i] = d_in[i];
    } else {
        bool used[64] = {false};
        for (int r = 0; r < 15; r++) {
            P[r] = nullptr;
            for (int j = 0; j < n_in && j < 64; j++) {
                if (!used[j] && in_sizes[j] == EXPECTED[r]) { P[r] = d_in[j]; used[j] = true; break; }
            }
        }
    }

    const float* x   = (const float*)P[0];
    const float* Ws  = (const float*)P[2];
    const float* bs  = (const float*)P[3];
    const float* Wh  = (const float*)P[4];
    const float* bh  = (const float*)P[5];
    const float* Wo1 = (const float*)P[6];
    const float* Wo2 = (const float*)P[7];
    const float* bo2 = (const float*)P[8];
    const float* W1  = (const float*)P[9];
    const float* b1  = (const float*)P[10];
    const float* W2  = (const float*)P[11];
    const float* b2  = (const float*)P[12];
    const float* W3  = (const float*)P[13];
    const float* b3  = (const float*)P[14];
    float* dout = (float*)d_out;

    float *p_aggr, *p_out, *p_t, *p_y, *p_c3;
    cudaGetSymbolAddress((void**)&p_aggr, g_aggr);
    cudaGetSymbolAddress((void**)&p_out,  g_out);
    cudaGetSymbolAddress((void**)&p_t,    g_t);
    cudaGetSymbolAddress((void**)&p_y,    g_y);
    cudaGetSymbolAddress((void**)&p_c3,   g_c3);

    const int SMEM_KNN = 8192 * 4 + 8 * 1024 * 4 + 8 * CAND * 8;   // 73728
    const int SMEM_OUT = (48 * 132 + 96 * 96 + 44 * 96) * 4;       // 79104
    const int SMEM_B   = (96 * 132 + 96 * 128) * 4;                // 99840
    const int SMEM_C   = (64 * 132 + 128 * 96) * 4;                // 82944
    const int SMEM_Z   = (96 * 132 + 96 * 96) * 4;                 // 87552
    cudaFuncSetAttribute(knn_kernel, cudaFuncAttributeMaxDynamicSharedMemorySize, SMEM_KNN);
    cudaFuncSetAttribute(gemm_out_k, cudaFuncAttributeMaxDynamicSharedMemorySize, SMEM_OUT);
    cudaFuncSetAttribute(gemm_k<96, 128, 96, 256, true, false>,
                         cudaFuncAttributeMaxDynamicSharedMemorySize, SMEM_B);
    cudaFuncSetAttribute(gemm_k<128, 96, 64, 192, true, false>,
                         cudaFuncAttributeMaxDynamicSharedMemorySize, SMEM_C);
    cudaFuncSetAttribute(gemm_k<96, 96, 96, 192, true, true>,
                         cudaFuncAttributeMaxDynamicSharedMemorySize, SMEM_Z);

    sh_kernel<<<Nq / 32, 256>>>(x, Ws, bs, Wh, bh);
    nop_k<<<1, 32>>>();
    nop_k<<<1, 32>>>();
    // knn in the 4th launch slot (the one ncu captures)
    knn_kernel<<<Nq / 32, 256, SMEM_KNN>>>(dout);
    gemm_out_k<<<Nq / 128, 192, SMEM_OUT>>>(x, p_aggr, Wo1, Wo2, bo2, p_out);
    gemm_k<96, 128, 96, 256, true, false><<<Nq / 128, 256, SMEM_B>>>(p_out, W1, b1, p_t);
    gemm_k<128, 96, 64, 192, true, false><<<Nq / 128, 192, SMEM_C>>>(p_t, W2, b2, p_y);
    stats1_k<<<Bq * 16, 192>>>();
    stats2_k<<<Bq, 96>>>(W3, b3);
    gemm_k<96, 96, 96, 192, true, true><<<Nq / 128, 192, SMEM_Z>>>(p_y, W3 + 288 * 96, p_c3, dout);
}

// round 15
// speedup vs baseline: 1.6967x; 1.1088x over previous
#include <cuda_runtime.h>
#include <cstdint>

// ---------------- problem constants ----------------
#define Bq   16
#define Mq   2048
#define Kq   40
#define Nq   (Bq*Mq)      // 32768
#define INC  96
#define SDQ  4
#define PDQ  22
#define H1   128
#define CAND 128

typedef unsigned long long ull;

static const size_t ZOFF = (size_t)Nq * 96;        // floats before edge_index
static const size_t NKq  = (size_t)Nq * Kq;

// ---------------- device scratch ----------------
__device__ float g_s[Nq * SDQ];
__device__ float g_h[Nq * PDQ];
__device__ float g_aggr[Nq * 2 * PDQ];
__device__ float g_out[Nq * 96];
__device__ float g_t[Nq * H1];
__device__ float g_y[Nq * 96];
__device__ float g_c3[Bq * 96];
__device__ float g_part[Bq * 16 * 3 * 96];

__device__ __forceinline__ float fast_tanh(float v) {
    float e = __expf(2.f * v);
    return (e - 1.f) * __frcp_rn(e + 1.f);
}

// ---------------- packed f32x2 helpers (sm_103a) ----------------
__device__ __forceinline__ ull pack2(float a, float b) {
    ull r; asm("mov.b64 %0, {%1,%2};" : "=l"(r) : "f"(a), "f"(b)); return r;
}
__device__ __forceinline__ float2 unpack2(ull v) {
    float2 f; asm("mov.b64 {%0,%1}, %2;" : "=f"(f.x), "=f"(f.y) : "l"(v)); return f;
}
__device__ __forceinline__ ull fma2(ull a, ull b, ull c) {
    ull d; asm("fma.rn.f32x2 %0, %1, %2, %3;" : "=l"(d) : "l"(a), "l"(b), "l"(c)); return d;
}
__device__ __forceinline__ ull add2(ull a, ull b) {
    ull d; asm("add.rn.f32x2 %0, %1, %2;" : "=l"(d) : "l"(a), "l"(b)); return d;
}
__device__ __forceinline__ ull mul2(ull a, ull b) {
    ull d; asm("mul.rn.f32x2 %0, %1, %2;" : "=l"(d) : "l"(a), "l"(b)); return d;
}

// packed pair distance over NEGATED neighbor coords: per-element IEEE-rn ops
// in the SAME order as the scalar d2exact chain -> bit-identical results.
__device__ __forceinline__ ull d2pair(ull sqx2, ull sqy2, ull sqz2, ull sqw2,
                                      ull nx, ull ny, ull nz, ull nw) {
    ull px = add2(sqx2, nx), py = add2(sqy2, ny);
    ull pz = add2(sqz2, nz), pw = add2(sqw2, nw);
    return fma2(px, px, fma2(py, py, fma2(pz, pz, mul2(pw, pw))));
}

// ---- bitonic sort of NR*32 u64 keys, ascending (warp-collective) ----
template<int NR>
__device__ __forceinline__ void bitonic_sort(ull* v, int lane)
{
    #pragma unroll
    for (int kk = 2; kk <= NR * 32; kk <<= 1) {
        #pragma unroll
        for (int j = kk >> 1; j > 0; j >>= 1) {
            if (j >= 32) {
                int qx = j >> 5;
                #pragma unroll
                for (int q = 0; q < NR; q++) {
                    if ((q & qx) == 0) {
                        int e = q * 32 + lane;
                        bool up = ((e & kk) == 0);
                        ull a = v[q], b = v[q | qx];
                        bool sw2 = up ? (a > b) : (a < b);
                        if (sw2) { v[q] = b; v[q | qx] = a; }
                    }
                }
            } else {
                #pragma unroll
                for (int q = 0; q < NR; q++) {
                    int e = q * 32 + lane;
                    bool up = ((e & kk) == 0);
                    ull o = __shfl_xor_sync(0xffffffffu, v[q], j);
                    bool keepmin = (((lane & j) == 0) == up);
                    bool take = keepmin ? (o < v[q]) : (o > v[q]);
                    if (take) v[q] = o;
                }
            }
        }
    }
}

// ================= K0: s = x@W_s + b_s ; h = x@W_h + b_h =================
__global__ __launch_bounds__(256) void sh_kernel(
    const float* __restrict__ x,
    const float* __restrict__ Ws, const float* __restrict__ bs,
    const float* __restrict__ Wh, const float* __restrict__ bh)
{
    __shared__ float wsh[INC * 26];
    __shared__ float xs[32][INC];
    int tid = threadIdx.x;
    for (int idx = tid; idx < INC * 26; idx += 256) {
        int k = idx / 26, od = idx % 26;
        wsh[idx] = (od < SDQ) ? Ws[k * SDQ + od] : Wh[k * PDQ + (od - SDQ)];
    }
    const float* xb = x + (size_t)blockIdx.x * 32 * INC;
    for (int idx = tid; idx < 32 * INC / 4; idx += 256)
        ((float4*)xs)[idx] = ((const float4*)xb)[idx];
    __syncthreads();

    int w = tid >> 5, od = tid & 31;
    if (od < 26) {
        float bv = (od < SDQ) ? bs[od] : bh[od - SDQ];
        #pragma unroll
        for (int q = 0; q < 4; q++) {
            int nl = w * 4 + q;
            float acc = 0.f;
            #pragma unroll 8
            for (int k = 0; k < INC; k++) acc = fmaf(xs[nl][k], wsh[k * 26 + od], acc);
            int n = blockIdx.x * 32 + nl;
            if (od < SDQ) g_s[n * SDQ + od] = acc + bv;
            else          g_h[n * PDQ + (od - SDQ)] = acc + bv;
        }
    }
}

// ================= K1: kNN + weighted mean/max aggregation + edges =======
// R14 structure + (a) per-lane weight precompute (2 expf/query instead of 40),
// (b) mask-driven compaction walk (ffs over accept slots).
__global__ __launch_bounds__(256, 3) void knn_kernel(float* __restrict__ dout)
{
    extern __shared__ float dsm[];
    float* nsx = dsm;                 // 2048 (negated coords)
    float* nsy = dsm + 2048;
    float* nsz = dsm + 4096;
    float* nsw = dsm + 6144;
    unsigned* d16 = (unsigned*)(dsm + 8192);          // 8 warps * 1024 u32 (32KB)
    ull* cand = (ull*)(dsm + 8192 + 8 * 1024);        // 8 * 128 u64 (8KB)

    int tid  = threadIdx.x;
    int lane = tid & 31;
    int w    = tid >> 5;
    int ev     = blockIdx.x >> 6;                // 64 blocks / event
    int qbase0 = (blockIdx.x & 63) * 32;

    const float4* sev = (const float4*)(g_s + (size_t)ev * Mq * SDQ);
    for (int j = tid; j < Mq; j += 256) {
        float4 s = sev[j];
        nsx[j] = -s.x; nsy[j] = -s.y; nsz[j] = -s.z; nsw[j] = -s.w;
    }
    __syncthreads();

    unsigned* myd16 = d16 + w * 1024;
    ull* mycand = cand + w * CAND;
    const uint4* dv16 = (const uint4*)myd16;
    const float* hev = g_h + (size_t)ev * Mq * PDQ;
    int evM = ev * Mq;
    float Twarm = -1.f;

    for (int q = 0; q < 4; q++) {
        int qloc = qbase0 + w * 4 + q;
        int i = evM + qloc;
        float sqx = -nsx[qloc], sqy = -nsy[qloc], sqz = -nsz[qloc], sqw = -nsw[qloc];
        ull sqx2 = pack2(sqx, sqx), sqy2 = pack2(sqy, sqy);
        ull sqz2 = pack2(sqz, sqz), sqw2 = pack2(sqw, sqw);

        // ---- distance pass: packed f32x2; fsum only for first query ----
        float T;
        if (Twarm > 0.f) {
            #pragma unroll 8
            for (int t = 0; t < 32; t++) {
                int p = lane + 32 * t;
                ull d2p = d2pair(sqx2, sqy2, sqz2, sqw2,
                                 *(const ull*)&nsx[2 * p], *(const ull*)&nsy[2 * p],
                                 *(const ull*)&nsz[2 * p], *(const ull*)&nsw[2 * p]);
                float2 dd = unpack2(d2p);
                myd16[p] = (__float_as_uint(dd.x) >> 16) | (__float_as_uint(dd.y) & 0xffff0000u);
            }
            T = Twarm;
        } else {
            ull fs2 = pack2(0.f, 0.f);
            #pragma unroll 8
            for (int t = 0; t < 32; t++) {
                int p = lane + 32 * t;
                ull d2p = d2pair(sqx2, sqy2, sqz2, sqw2,
                                 *(const ull*)&nsx[2 * p], *(const ull*)&nsy[2 * p],
                                 *(const ull*)&nsz[2 * p], *(const ull*)&nsw[2 * p]);
                float2 dd = unpack2(d2p);
                myd16[p] = (__float_as_uint(dd.x) >> 16) | (__float_as_uint(dd.y) & 0xffff0000u);
                fs2 = add2(fs2, d2p);
            }
            float2 fsp = unpack2(fs2);
            float fsum = fsp.x + fsp.y;
            #pragma unroll
            for (int o = 16; o; o >>= 1) fsum += __shfl_xor_sync(0xffffffffu, fsum, o);
            T = fsum * (0.20f / 2048.f);
        }
        __syncwarp();

        // ---- threshold search: vectorized probes; count in [Kq, 64] ----
        float lo = 0.f, hi = 3.3e38f;
        unsigned T16 = 0u;
        bool found = false;
        for (int it = 0; it < 16 && !found; ++it) {
            T16 = __float_as_uint(T) >> 16;
            unsigned TT = T16 * 0x10001u;
            unsigned acc = 0;
            #pragma unroll
            for (int t4 = 0; t4 < 8; t4++) {
                uint4 u = dv16[lane + 32 * t4];
                acc = __vadd2(acc, __vsetleu2(u.x, TT));
                acc = __vadd2(acc, __vsetleu2(u.y, TT));
                acc = __vadd2(acc, __vsetleu2(u.z, TT));
                acc = __vadd2(acc, __vsetleu2(u.w, TT));
            }
            int c = (int)((acc & 0xffffu) + (acc >> 16));
            c = __reduce_add_sync(0xffffffffu, c);
            if (c >= Kq && c <= 64) { found = true; break; }
            if (c < Kq) {
                lo = T;
                float Tm = T * sqrtf(50.f / fmaxf((float)c, 2.f));
                if (hi < 3e38f) {
                    float wdt = hi - lo;
                    Tm = fminf(fmaxf(Tm, lo + 0.25f * wdt), lo + 0.75f * wdt);
                } else {
                    Tm = fmaxf(Tm, T * 1.5f);
                }
                T = Tm;
            } else {
                hi = T;
                float Tm = T * sqrtf(50.f / (float)c);
                float wdt = hi - lo;
                Tm = fminf(fmaxf(Tm, lo + 0.25f * wdt), lo + 0.75f * wdt);
                T = Tm;
            }
        }
        if (!found) {   // exact bisection in u16 space (guaranteed >= Kq)
            unsigned l = 0u, h = 0x7f80u;
            for (int it = 0; it < 18 && !found; ++it) {
                unsigned mid = l + ((h - l) >> 1);
                unsigned TT = mid * 0x10001u;
                unsigned acc = 0;
                #pragma unroll
                for (int t4 = 0; t4 < 8; t4++) {
                    uint4 u = dv16[lane + 32 * t4];
                    acc = __vadd2(acc, __vsetleu2(u.x, TT));
                    acc = __vadd2(acc, __vsetleu2(u.y, TT));
                    acc = __vadd2(acc, __vsetleu2(u.z, TT));
                    acc = __vadd2(acc, __vsetleu2(u.w, TT));
                }
                int cc = (int)((acc & 0xffffu) + (acc >> 16));
                cc = __reduce_add_sync(0xffffffffu, cc);
                if (cc >= Kq && cc <= 64) { T16 = mid; found = true; }
                else if (cc >= Kq) h = mid;
                else l = mid;
                if (!found && h - l <= 1u) { T16 = h; found = true; }
            }
        }
        Twarm = __uint_as_float((T16 << 16) | 0xffffu);

        // ---- re-count in per-lane layout; build accept-slot mask ----
        unsigned TT = T16 * 0x10001u;
        unsigned accv = 0u, tmask = 0u;
        #pragma unroll
        for (int t = 0; t < 32; t++) {
            unsigned r2 = __vsetleu2(myd16[lane + 32 * t], TT);
            accv = __vadd2(accv, r2);
            if (r2) tmask |= (1u << t);
        }
        int cnt = (int)((accv & 0xffffu) + (accv >> 16));
        int incl = cnt;
        #pragma unroll
        for (int d = 1; d < 32; d <<= 1) {
            int n = __shfl_up_sync(0xffffffffu, incl, d);
            if (lane >= d) incl += n;
        }
        int pos = incl - cnt;                        // exclusive offset
        int C = __shfl_sync(0xffffffffu, incl, 31);  // total accepted
        if (C > CAND) C = CAND;

        // ---- sparse walk over accept slots only ----
        while (tmask) {
            int t = __ffs(tmask) - 1;
            tmask &= tmask - 1u;
            int p = lane + 32 * t;
            unsigned u = myd16[p];
            bool a0 = (u & 0xffffu) <= T16;
            bool a1 = (u >> 16) <= T16;
            ull d2p = d2pair(sqx2, sqy2, sqz2, sqw2,
                             *(const ull*)&nsx[2 * p], *(const ull*)&nsy[2 * p],
                             *(const ull*)&nsz[2 * p], *(const ull*)&nsw[2 * p]);
            float2 dd = unpack2(d2p);
            if (a0) {
                if (pos < CAND)
                    mycand[pos] = ((ull)__float_as_uint(dd.x) << 32) | (unsigned)(2 * p);
                pos++;
            }
            if (a1) {
                if (pos < CAND)
                    mycand[pos] = ((ull)__float_as_uint(dd.y) << 32) | (unsigned)(2 * p + 1);
                pos++;
            }
        }
        __syncwarp();

        // ---- sort: 64-key fast path, 128-key fallback ----
        ull v[4];
        if (C <= 64) {
            #pragma unroll
            for (int qq = 0; qq < 2; qq++) {
                int e = qq * 32 + lane;
                v[qq] = (e < C) ? mycand[e] : ~0ull;
            }
            bitonic_sort<2>(v, lane);
        } else {
            #pragma unroll
            for (int qq = 0; qq < 4; qq++) {
                int e = qq * 32 + lane;
                v[qq] = (e < C) ? mycand[e] : ~0ull;
            }
            bitonic_sort<4>(v, lane);
        }

        // ---- edge output (coalesced) ----
        float* esrc = dout + ZOFF + (size_t)i * Kq;
        float* etgt = esrc + NKq;
        unsigned j0 = (unsigned)(v[0] & 0xffffffffu);
        unsigned j1 = (unsigned)(v[1] & 0xffffffffu);
        esrc[lane] = (float)(evM + (int)j0);
        if (lane < 8)  esrc[32 + lane] = (float)(evM + (int)j1);
        if (lane < 10) *(float4*)&etgt[4 * lane] =
            make_float4((float)i, (float)i, (float)i, (float)i);

        // ---- weight precompute: lane r holds rank r / r+32 ----
        float w0 = __expf(-10.f * __uint_as_float((unsigned)(v[0] >> 32)));
        float w1 = __expf(-10.f * __uint_as_float((unsigned)(v[1] >> 32)));

        // ---- top-40 broadcast aggregation (weights via shfl) ----
        float meanAcc = 0.f;
        float maxAcc  = __int_as_float(0xff800000);
        #pragma unroll 8
        for (int r = 0; r < Kq; r++) {
            unsigned jj = (r < 32) ? __shfl_sync(0xffffffffu, j0, r)
                                   : __shfl_sync(0xffffffffu, j1, r - 32);
            float wgt   = (r < 32) ? __shfl_sync(0xffffffffu, w0, r)
                                   : __shfl_sync(0xffffffffu, w1, r - 32);
            if (lane < PDQ) {
                float msg = hev[(size_t)jj * PDQ + lane] * wgt;
                meanAcc += msg;
                maxAcc = fmaxf(maxAcc, msg);
            }
        }
        if (lane < PDQ) {
            float* ag = g_aggr + (size_t)i * 2 * PDQ;
            ag[lane]       = meanAcc * (1.f / (float)Kq);
            ag[PDQ + lane] = maxAcc;
        }
        __syncwarp();
    }
}

// ================= row-tiled SIMT GEMM (R8 config: 8x8 f32x2, 2 CTAs) =====
template<int KD, int OC, int KCH, int NT, bool DOTANH, bool EVBIAS>
__global__ __launch_bounds__(NT, 2) void gemm_k(
    const float* __restrict__ A, const float* __restrict__ W,
    const float* __restrict__ bias, float* __restrict__ Cf)
{
    constexpr int RT = 128, AST = 132, CG = OC / 8;
    extern __shared__ float sm[];
    float* As  = sm;
    float* Wsm = sm + KCH * AST;
    int tid = threadIdx.x;
    int rowBase = blockIdx.x * RT;

    for (int idx = tid; idx < KD * OC / 4; idx += NT)
        ((float4*)Wsm)[idx] = ((const float4*)W)[idx];

    int cg = tid % CG, rg = tid / CG;
    int r0 = rg * 8, c0 = cg * 8;

    ull accp[4][8];
    {
        const float* bp = EVBIAS ? (bias + (rowBase >> 11) * 96) : bias;
        #pragma unroll
        for (int cc = 0; cc < 8; cc++) {
            ull bv = pack2(bp[c0 + cc], bp[c0 + cc]);
            #pragma unroll
            for (int rp = 0; rp < 4; rp++) accp[rp][cc] = bv;
        }
    }

    for (int kc = 0; kc < KD; kc += KCH) {
        __syncthreads();
        for (int idx = tid; idx < RT * KCH; idx += NT) {
            int r = idx / KCH, k = idx - r * KCH;
            As[k * AST + r] = A[(size_t)(rowBase + r) * KD + kc + k];
        }
        __syncthreads();
        #pragma unroll 8
        for (int k = 0; k < KCH; k++) {
            ulonglong2 a01 = *(const ulonglong2*)&As[k * AST + r0];
            ulonglong2 a23 = *(const ulonglong2*)&As[k * AST + r0 + 4];
            float4 w0 = *(const float4*)&Wsm[(kc + k) * OC + c0];
            float4 w1 = *(const float4*)&Wsm[(kc + k) * OC + c0 + 4];
            ull ap[4] = {a01.x, a01.y, a23.x, a23.y};
            ull wp[8] = {pack2(w0.x, w0.x), pack2(w0.y, w0.y),
                         pack2(w0.z, w0.z), pack2(w0.w, w0.w),
                         pack2(w1.x, w1.x), pack2(w1.y, w1.y),
                         pack2(w1.z, w1.z), pack2(w1.w, w1.w)};
            #pragma unroll
            for (int rp = 0; rp < 4; rp++)
                #pragma unroll
                for (int cc = 0; cc < 8; cc++)
                    accp[rp][cc] = fma2(ap[rp], wp[cc], accp[rp][cc]);
        }
    }

    #pragma unroll
    for (int rp = 0; rp < 4; rp++) {
        float vlo[8], vhi[8];
        #pragma unroll
        for (int cc = 0; cc < 8; cc++) {
            float2 f = unpack2(accp[rp][cc]);
            vlo[cc] = DOTANH ? fast_tanh(f.x) : f.x;
            vhi[cc] = DOTANH ? fast_tanh(f.y) : f.y;
        }
        size_t ro0 = (size_t)(rowBase + r0 + 2 * rp) * OC + c0;
        size_t ro1 = ro0 + OC;
        *(float4*)&Cf[ro0]     = make_float4(vlo[0], vlo[1], vlo[2], vlo[3]);
        *(float4*)&Cf[ro0 + 4] = make_float4(vlo[4], vlo[5], vlo[6], vlo[7]);
        *(float4*)&Cf[ro1]     = make_float4(vhi[0], vhi[1], vhi[2], vhi[3]);
        *(float4*)&Cf[ro1 + 4] = make_float4(vhi[4], vhi[5], vhi[6], vhi[7]);
    }
}

// ================= K2a: out = x@W_o1 + aggr@W_o2 + b_o2 (R8 config) =======
__global__ __launch_bounds__(192, 2) void gemm_out_k(
    const float* __restrict__ x, const float* __restrict__ aggr,
    const float* __restrict__ Wo1, const float* __restrict__ Wo2,
    const float* __restrict__ bias, float* __restrict__ outp)
{
    constexpr int RT = 128, AST = 132, NT = 192, OC = 96;
    extern __shared__ float sm[];
    float* As  = sm;                     // 48*132
    float* Ws1 = sm + 48 * AST;          // 96*96
    float* Ws2 = Ws1 + 96 * 96;          // 44*96
    int tid = threadIdx.x;
    int rowBase = blockIdx.x * RT;

    for (int idx = tid; idx < 96 * 96 / 4; idx += NT)
        ((float4*)Ws1)[idx] = ((const float4*)Wo1)[idx];
    for (int idx = tid; idx < 44 * 96 / 4; idx += NT)
        ((float4*)Ws2)[idx] = ((const float4*)Wo2)[idx];

    int cg = tid % 12, rg = tid / 12;
    int r0 = rg * 8, c0 = cg * 8;

    ull accp[4][8];
    #pragma unroll
    for (int cc = 0; cc < 8; cc++) {
        ull bv = pack2(bias[c0 + cc], bias[c0 + cc]);
        #pragma unroll
        for (int rp = 0; rp < 4; rp++) accp[rp][cc] = bv;
    }

    #pragma unroll
    for (int chunk = 0; chunk < 2; chunk++) {
        __syncthreads();
        for (int idx = tid; idx < RT * 48; idx += NT) {
            int r = idx / 48, k = idx - r * 48;
            As[k * AST + r] = x[(size_t)(rowBase + r) * 96 + chunk * 48 + k];
        }
        __syncthreads();
        #pragma unroll 8
        for (int k = 0; k < 48; k++) {
            ulonglong2 a01 = *(const ulonglong2*)&As[k * AST + r0];
            ulonglong2 a23 = *(const ulonglong2*)&As[k * AST + r0 + 4];
            float4 w0 = *(const float4*)&Ws1[(chunk * 48 + k) * OC + c0];
            float4 w1 = *(const float4*)&Ws1[(chunk * 48 + k) * OC + c0 + 4];
            ull ap[4] = {a01.x, a01.y, a23.x, a23.y};
            ull wp[8] = {pack2(w0.x, w0.x), pack2(w0.y, w0.y),
                         pack2(w0.z, w0.z), pack2(w0.w, w0.w),
                         pack2(w1.x, w1.x), pack2(w1.y, w1.y),
                         pack2(w1.z, w1.z), pack2(w1.w, w1.w)};
            #pragma unroll
            for (int rp = 0; rp < 4; rp++)
                #pragma unroll
                for (int cc = 0; cc < 8; cc++)
                    accp[rp][cc] = fma2(ap[rp], wp[cc], accp[rp][cc]);
        }
    }
    __syncthreads();
    for (int idx = tid; idx < RT * 44; idx += NT) {
        int r = idx / 44, k = idx - r * 44;
        As[k * AST + r] = aggr[(size_t)(rowBase + r) * 44 + k];
    }
    __syncthreads();
    #pragma unroll 4
    for (int k = 0; k < 44; k++) {
        ulonglong2 a01 = *(const ulonglong2*)&As[k * AST + r0];
        ulonglong2 a23 = *(const ulonglong2*)&As[k * AST + r0 + 4];
        float4 w0 = *(const float4*)&Ws2[k * OC + c0];
        float4 w1 = *(const float4*)&Ws2[k * OC + c0 + 4];
        ull ap[4] = {a01.x, a01.y, a23.x, a23.y};
        ull wp[8] = {pack2(w0.x, w0.x), pack2(w0.y, w0.y),
                     pack2(w0.z, w0.z), pack2(w0.w, w0.w),
                     pack2(w1.x, w1.x), pack2(w1.y, w1.y),
                     pack2(w1.z, w1.z), pack2(w1.w, w1.w)};
        #pragma unroll
        for (int rp = 0; rp < 4; rp++)
            #pragma unroll
            for (int cc = 0; cc < 8; cc++)
                accp[rp][cc] = fma2(ap[rp], wp[cc], accp[rp][cc]);
    }

    #pragma unroll
    for (int rp = 0; rp < 4; rp++) {
        float vlo[8], vhi[8];
        #pragma unroll
        for (int cc = 0; cc < 8; cc++) {
            float2 f = unpack2(accp[rp][cc]);
            vlo[cc] = f.x; vhi[cc] = f.y;
        }
        size_t ro0 = (size_t)(rowBase + r0 + 2 * rp) * OC + c0;
        size_t ro1 = ro0 + OC;
        *(float4*)&outp[ro0]     = make_float4(vlo[0], vlo[1], vlo[2], vlo[3]);
        *(float4*)&outp[ro0 + 4] = make_float4(vlo[4], vlo[5], vlo[6], vlo[7]);
        *(float4*)&outp[ro1]     = make_float4(vhi[0], vhi[1], vhi[2], vhi[3]);
        *(float4*)&outp[ro1 + 4] = make_float4(vhi[4], vhi[5], vhi[6], vhi[7]);
    }
}

// ================= K3a: per-(event,chunk) partial mean/min/max ===========
__global__ __launch_bounds__(192) void stats1_k()
{
    int ev = blockIdx.x >> 4, ch = blockIdx.x & 15;
    int tid = threadIdx.x;
    int d = tid % 96, half = tid / 96;
    __shared__ float red[3][192];

    const float* yb = g_y + (size_t)ev * Mq * 96 + (size_t)ch * 128 * 96;
    float sm = 0.f, mn = __int_as_float(0x7f800000), mx = __int_as_float(0xff800000);
    for (int r = half; r < 128; r += 2) {
        float v = yb[(size_t)r * 96 + d];
        sm += v; mn = fminf(mn, v); mx = fmaxf(mx, v);
    }
    red[0][tid] = sm; red[1][tid] = mn; red[2][tid] = mx;
    __syncthreads();
    if (tid < 96) {
        float* p = g_part + ((size_t)(ev * 16 + ch) * 3) * 96;
        p[tid]        = red[0][tid] + red[0][tid + 96];
        p[96 + tid]   = fminf(red[1][tid], red[1][tid + 96]);
        p[192 + tid]  = fmaxf(red[2][tid], red[2][tid + 96]);
    }
}

// ================= K3b: reduce partials + stats@W3[0:288]+b3 =============
__global__ __launch_bounds__(96) void stats2_k(
    const float* __restrict__ W3, const float* __restrict__ b3)
{
    int ev = blockIdx.x, tid = threadIdx.x;
    __shared__ float st[288];

    float sm = 0.f, mn = __int_as_float(0x7f800000), mx = __int_as_float(0xff800000);
    for (int ch = 0; ch < 16; ch++) {
        const float* p = g_part + ((size_t)(ev * 16 + ch) * 3) * 96;
        sm += p[tid];
        mn = fminf(mn, p[96 + tid]);
        mx = fmaxf(mx, p[192 + tid]);
    }
    st[tid]       = sm * (1.f / (float)Mq);
    st[96 + tid]  = mn;
    st[192 + tid] = mx;
    __syncthreads();

    float acc = b3[tid];
    #pragma unroll 4
    for (int k = 0; k < 288; k++) acc = fmaf(st[k], W3[(size_t)k * 96 + tid], acc);
    g_c3[ev * 96 + tid] = acc;
}

// ================= host launcher =========================================
extern "C" void kernel_launch(void* const* d_in, const int* in_sizes, int n_in,
                              void* d_out, int out_size)
{
    (void)out_size;
    static const int EXPECTED[15] = {
        3145728, 32768, 384, 4, 2112, 22, 9216, 4224, 96, 12288, 128, 12288, 96, 36864, 96
    };
    const void* P[15];
    bool ok = (n_in >= 15);
    if (ok) for (int i = 0; i < 15; i++) if (in_sizes[i] != EXPECTED[i]) { ok = false; break; }
    if (ok) {
        for (int i = 0; i < 15; i++) P[i] = d_in[i];
    } else {
        bool used[64] = {false};
        for (int r = 0; r < 15; r++) {
            P[r] = nullptr;
            for (int j = 0; j < n_in && j < 64; j++) {
                if (!used[j] && in_sizes[j] == EXPECTED[r]) { P[r] = d_in[j]; used[j] = true; break; }
            }
        }
    }

    const float* x   = (const float*)P[0];
    const float* Ws  = (const float*)P[2];
    const float* bs  = (const float*)P[3];
    const float* Wh  = (const float*)P[4];
    const float* bh  = (const float*)P[5];
    const float* Wo1 = (const float*)P[6];
    const float* Wo2 = (const float*)P[7];
    const float* bo2 = (const float*)P[8];
    const float* W1  = (const float*)P[9];
    const float* b1  = (const float*)P[10];
    const float* W2  = (const float*)P[11];
    const float* b2  = (const float*)P[12];
    const float* W3  = (const float*)P[13];
    const float* b3  = (const float*)P[14];
    float* dout = (float*)d_out;

    float *p_aggr, *p_out, *p_t, *p_y, *p_c3;
    cudaGetSymbolAddress((void**)&p_aggr, g_aggr);
    cudaGetSymbolAddress((void**)&p_out,  g_out);
    cudaGetSymbolAddress((void**)&p_t,    g_t);
    cudaGetSymbolAddress((void**)&p_y,    g_y);
    cudaGetSymbolAddress((void**)&p_c3,   g_c3);

    const int SMEM_KNN = 8192 * 4 + 8 * 1024 * 4 + 8 * CAND * 8;   // 73728
    const int SMEM_OUT = (48 * 132 + 96 * 96 + 44 * 96) * 4;       // 79104
    const int SMEM_B   = (96 * 132 + 96 * 128) * 4;                // 99840
    const int SMEM_C   = (64 * 132 + 128 * 96) * 4;                // 82944
    const int SMEM_Z   = (96 * 132 + 96 * 96) * 4;                 // 87552
    cudaFuncSetAttribute(knn_kernel, cudaFuncAttributeMaxDynamicSharedMemorySize, SMEM_KNN);
    cudaFuncSetAttribute(gemm_out_k, cudaFuncAttributeMaxDynamicSharedMemorySize, SMEM_OUT);
    cudaFuncSetAttribute(gemm_k<96, 128, 96, 256, true, false>,
                         cudaFuncAttributeMaxDynamicSharedMemorySize, SMEM_B);
    cudaFuncSetAttribute(gemm_k<128, 96, 64, 192, true, false>,
                         cudaFuncAttributeMaxDynamicSharedMemorySize, SMEM_C);
    cudaFuncSetAttribute(gemm_k<96, 96, 96, 192, true, true>,
                         cudaFuncAttributeMaxDynamicSharedMemorySize, SMEM_Z);

    sh_kernel<<<Nq / 32, 256>>>(x, Ws, bs, Wh, bh);
    knn_kernel<<<Nq / 32, 256, SMEM_KNN>>>(dout);
    gemm_out_k<<<Nq / 128, 192, SMEM_OUT>>>(x, p_aggr, Wo1, Wo2, bo2, p_out);
    gemm_k<96, 128, 96, 256, true, false><<<Nq / 128, 256, SMEM_B>>>(p_out, W1, b1, p_t);
    gemm_k<128, 96, 64, 192, true, false><<<Nq / 128, 192, SMEM_C>>>(p_t, W2, b2, p_y);
    stats1_k<<<Bq * 16, 192>>>();
    stats2_k<<<Bq, 96>>>(W3, b3);
    gemm_k<96, 96, 96, 192, true, true><<<Nq / 128, 192, SMEM_Z>>>(p_y, W3 + 288 * 96, p_c3, dout);
}

// round 16
// speedup vs baseline: 1.7778x; 1.0478x over previous
#include <cuda_runtime.h>
#include <cstdint>

// ---------------- problem constants ----------------
#define Bq   16
#define Mq   2048
#define Kq   40
#define Nq   (Bq*Mq)      // 32768
#define INC  96
#define SDQ  4
#define PDQ  22
#define H1   128
#define CAND 128

typedef unsigned long long ull;

static const size_t ZOFF = (size_t)Nq * 96;        // floats before edge_index
static const size_t NKq  = (size_t)Nq * Kq;

// ---------------- device scratch ----------------
__device__ float g_s[Nq * SDQ];
__device__ float g_h[Nq * PDQ];
__device__ float g_aggr[Nq * 2 * PDQ];
__device__ float g_out[Nq * 96];
__device__ float g_t[Nq * H1];
__device__ float g_y[Nq * 96];
__device__ float g_c3[Bq * 96];
__device__ float g_part[Bq * 16 * 3 * 96];

__device__ __forceinline__ float fast_tanh(float v) {
    float e = __expf(2.f * v);
    return (e - 1.f) * __frcp_rn(e + 1.f);
}

// ---------------- packed f32x2 helpers (sm_103a) ----------------
__device__ __forceinline__ ull pack2(float a, float b) {
    ull r; asm("mov.b64 %0, {%1,%2};" : "=l"(r) : "f"(a), "f"(b)); return r;
}
__device__ __forceinline__ float2 unpack2(ull v) {
    float2 f; asm("mov.b64 {%0,%1}, %2;" : "=f"(f.x), "=f"(f.y) : "l"(v)); return f;
}
__device__ __forceinline__ ull fma2(ull a, ull b, ull c) {
    ull d; asm("fma.rn.f32x2 %0, %1, %2, %3;" : "=l"(d) : "l"(a), "l"(b), "l"(c)); return d;
}
__device__ __forceinline__ ull add2(ull a, ull b) {
    ull d; asm("add.rn.f32x2 %0, %1, %2;" : "=l"(d) : "l"(a), "l"(b)); return d;
}
__device__ __forceinline__ ull mul2(ull a, ull b) {
    ull d; asm("mul.rn.f32x2 %0, %1, %2;" : "=l"(d) : "l"(a), "l"(b)); return d;
}

// packed pair distance over NEGATED neighbor coords: per-element IEEE-rn ops
// in the SAME order as the scalar d2exact chain -> bit-identical results.
__device__ __forceinline__ ull d2pair(ull sqx2, ull sqy2, ull sqz2, ull sqw2,
                                      ull nx, ull ny, ull nz, ull nw) {
    ull px = add2(sqx2, nx), py = add2(sqy2, ny);
    ull pz = add2(sqz2, nz), pw = add2(sqw2, nw);
    return fma2(px, px, fma2(py, py, fma2(pz, pz, mul2(pw, pw))));
}

// ---- bitonic sort of NR*32 u64 keys, ascending (warp-collective) ----
template<int NR>
__device__ __forceinline__ void bitonic_sort(ull* v, int lane)
{
    #pragma unroll
    for (int kk = 2; kk <= NR * 32; kk <<= 1) {
        #pragma unroll
        for (int j = kk >> 1; j > 0; j >>= 1) {
            if (j >= 32) {
                int qx = j >> 5;
                #pragma unroll
                for (int q = 0; q < NR; q++) {
                    if ((q & qx) == 0) {
                        int e = q * 32 + lane;
                        bool up = ((e & kk) == 0);
                        ull a = v[q], b = v[q | qx];
                        bool sw2 = up ? (a > b) : (a < b);
                        if (sw2) { v[q] = b; v[q | qx] = a; }
                    }
                }
            } else {
                #pragma unroll
                for (int q = 0; q < NR; q++) {
                    int e = q * 32 + lane;
                    bool up = ((e & kk) == 0);
                    ull o = __shfl_xor_sync(0xffffffffu, v[q], j);
                    bool keepmin = (((lane & j) == 0) == up);
                    bool take = keepmin ? (o < v[q]) : (o > v[q]);
                    if (take) v[q] = o;
                }
            }
        }
    }
}

// ================= K0: s = x@W_s + b_s ; h = x@W_h + b_h =================
__global__ __launch_bounds__(256) void sh_kernel(
    const float* __restrict__ x,
    const float* __restrict__ Ws, const float* __restrict__ bs,
    const float* __restrict__ Wh, const float* __restrict__ bh)
{
    __shared__ float wsh[INC * 26];
    __shared__ float xs[32][INC];
    int tid = threadIdx.x;
    for (int idx = tid; idx < INC * 26; idx += 256) {
        int k = idx / 26, od = idx % 26;
        wsh[idx] = (od < SDQ) ? Ws[k * SDQ + od] : Wh[k * PDQ + (od - SDQ)];
    }
    const float* xb = x + (size_t)blockIdx.x * 32 * INC;
    for (int idx = tid; idx < 32 * INC / 4; idx += 256)
        ((float4*)xs)[idx] = ((const float4*)xb)[idx];
    __syncthreads();

    int w = tid >> 5, od = tid & 31;
    if (od < 26) {
        float bv = (od < SDQ) ? bs[od] : bh[od - SDQ];
        #pragma unroll
        for (int q = 0; q < 4; q++) {
            int nl = w * 4 + q;
            float acc = 0.f;
            #pragma unroll 8
            for (int k = 0; k < INC; k++) acc = fmaf(xs[nl][k], wsh[k * 26 + od], acc);
            int n = blockIdx.x * 32 + nl;
            if (od < SDQ) g_s[n * SDQ + od] = acc + bv;
            else          g_h[n * PDQ + (od - SDQ)] = acc + bv;
        }
    }
}

// ================= K1: kNN + weighted mean/max aggregation + edges =======
// 2 queries/warp (grid 2048) for finer wave granularity; R15 inner machinery.
__global__ __launch_bounds__(256, 3) void knn_kernel(float* __restrict__ dout)
{
    extern __shared__ float dsm[];
    float* nsx = dsm;                 // 2048 (negated coords)
    float* nsy = dsm + 2048;
    float* nsz = dsm + 4096;
    float* nsw = dsm + 6144;
    unsigned* d16 = (unsigned*)(dsm + 8192);          // 8 warps * 1024 u32 (32KB)
    ull* cand = (ull*)(dsm + 8192 + 8 * 1024);        // 8 * 128 u64 (8KB)

    int tid  = threadIdx.x;
    int lane = tid & 31;
    int w    = tid >> 5;
    int ev     = blockIdx.x >> 7;                // 128 blocks / event
    int qbase0 = (blockIdx.x & 127) * 16;

    const float4* sev = (const float4*)(g_s + (size_t)ev * Mq * SDQ);
    for (int j = tid; j < Mq; j += 256) {
        float4 s = sev[j];
        nsx[j] = -s.x; nsy[j] = -s.y; nsz[j] = -s.z; nsw[j] = -s.w;
    }
    __syncthreads();

    unsigned* myd16 = d16 + w * 1024;
    ull* mycand = cand + w * CAND;
    const uint4* dv16 = (const uint4*)myd16;
    const float* hev = g_h + (size_t)ev * Mq * PDQ;
    int evM = ev * Mq;
    float Twarm = -1.f;

    for (int q = 0; q < 2; q++) {
        int qloc = qbase0 + w * 2 + q;
        int i = evM + qloc;
        float sqx = -nsx[qloc], sqy = -nsy[qloc], sqz = -nsz[qloc], sqw = -nsw[qloc];
        ull sqx2 = pack2(sqx, sqx), sqy2 = pack2(sqy, sqy);
        ull sqz2 = pack2(sqz, sqz), sqw2 = pack2(sqw, sqw);

        // ---- distance pass: packed f32x2; fsum only for first query ----
        float T;
        if (Twarm > 0.f) {
            #pragma unroll 8
            for (int t = 0; t < 32; t++) {
                int p = lane + 32 * t;
                ull d2p = d2pair(sqx2, sqy2, sqz2, sqw2,
                                 *(const ull*)&nsx[2 * p], *(const ull*)&nsy[2 * p],
                                 *(const ull*)&nsz[2 * p], *(const ull*)&nsw[2 * p]);
                float2 dd = unpack2(d2p);
                myd16[p] = (__float_as_uint(dd.x) >> 16) | (__float_as_uint(dd.y) & 0xffff0000u);
            }
            T = Twarm;
        } else {
            ull fs2 = pack2(0.f, 0.f);
            #pragma unroll 8
            for (int t = 0; t < 32; t++) {
                int p = lane + 32 * t;
                ull d2p = d2pair(sqx2, sqy2, sqz2, sqw2,
                                 *(const ull*)&nsx[2 * p], *(const ull*)&nsy[2 * p],
                                 *(const ull*)&nsz[2 * p], *(const ull*)&nsw[2 * p]);
                float2 dd = unpack2(d2p);
                myd16[p] = (__float_as_uint(dd.x) >> 16) | (__float_as_uint(dd.y) & 0xffff0000u);
                fs2 = add2(fs2, d2p);
            }
            float2 fsp = unpack2(fs2);
            float fsum = fsp.x + fsp.y;
            #pragma unroll
            for (int o = 16; o; o >>= 1) fsum += __shfl_xor_sync(0xffffffffu, fsum, o);
            T = fsum * (0.20f / 2048.f);
        }
        __syncwarp();

        // ---- threshold search: vectorized probes; count in [Kq, 64] ----
        float lo = 0.f, hi = 3.3e38f;
        unsigned T16 = 0u;
        bool found = false;
        for (int it = 0; it < 16 && !found; ++it) {
            T16 = __float_as_uint(T) >> 16;
            unsigned TT = T16 * 0x10001u;
            unsigned acc = 0;
            #pragma unroll
            for (int t4 = 0; t4 < 8; t4++) {
                uint4 u = dv16[lane + 32 * t4];
                acc = __vadd2(acc, __vsetleu2(u.x, TT));
                acc = __vadd2(acc, __vsetleu2(u.y, TT));
                acc = __vadd2(acc, __vsetleu2(u.z, TT));
                acc = __vadd2(acc, __vsetleu2(u.w, TT));
            }
            int c = (int)((acc & 0xffffu) + (acc >> 16));
            c = __reduce_add_sync(0xffffffffu, c);
            if (c >= Kq && c <= 64) { found = true; break; }
            if (c < Kq) {
                lo = T;
                float Tm = T * sqrtf(50.f / fmaxf((float)c, 2.f));
                if (hi < 3e38f) {
                    float wdt = hi - lo;
                    Tm = fminf(fmaxf(Tm, lo + 0.25f * wdt), lo + 0.75f * wdt);
                } else {
                    Tm = fmaxf(Tm, T * 1.5f);
                }
                T = Tm;
            } else {
                hi = T;
                float Tm = T * sqrtf(50.f / (float)c);
                float wdt = hi - lo;
                Tm = fminf(fmaxf(Tm, lo + 0.25f * wdt), lo + 0.75f * wdt);
                T = Tm;
            }
        }
        if (!found) {   // exact bisection in u16 space (guaranteed >= Kq)
            unsigned l = 0u, h = 0x7f80u;
            for (int it = 0; it < 18 && !found; ++it) {
                unsigned mid = l + ((h - l) >> 1);
                unsigned TT = mid * 0x10001u;
                unsigned acc = 0;
                #pragma unroll
                for (int t4 = 0; t4 < 8; t4++) {
                    uint4 u = dv16[lane + 32 * t4];
                    acc = __vadd2(acc, __vsetleu2(u.x, TT));
                    acc = __vadd2(acc, __vsetleu2(u.y, TT));
                    acc = __vadd2(acc, __vsetleu2(u.z, TT));
                    acc = __vadd2(acc, __vsetleu2(u.w, TT));
                }
                int cc = (int)((acc & 0xffffu) + (acc >> 16));
                cc = __reduce_add_sync(0xffffffffu, cc);
                if (cc >= Kq && cc <= 64) { T16 = mid; found = true; }
                else if (cc >= Kq) h = mid;
                else l = mid;
                if (!found && h - l <= 1u) { T16 = h; found = true; }
            }
        }
        Twarm = __uint_as_float((T16 << 16) | 0xffffu);

        // ---- re-count in per-lane layout; build accept-slot mask ----
        unsigned TT = T16 * 0x10001u;
        unsigned accv = 0u, tmask = 0u;
        #pragma unroll
        for (int t = 0; t < 32; t++) {
            unsigned r2 = __vsetleu2(myd16[lane + 32 * t], TT);
            accv = __vadd2(accv, r2);
            if (r2) tmask |= (1u << t);
        }
        int cnt = (int)((accv & 0xffffu) + (accv >> 16));
        int incl = cnt;
        #pragma unroll
        for (int d = 1; d < 32; d <<= 1) {
            int n = __shfl_up_sync(0xffffffffu, incl, d);
            if (lane >= d) incl += n;
        }
        int pos = incl - cnt;                        // exclusive offset
        int C = __shfl_sync(0xffffffffu, incl, 31);  // total accepted
        if (C > CAND) C = CAND;

        // ---- sparse walk over accept slots only ----
        while (tmask) {
            int t = __ffs(tmask) - 1;
            tmask &= tmask - 1u;
            int p = lane + 32 * t;
            unsigned u = myd16[p];
            bool a0 = (u & 0xffffu) <= T16;
            bool a1 = (u >> 16) <= T16;
            ull d2p = d2pair(sqx2, sqy2, sqz2, sqw2,
                             *(const ull*)&nsx[2 * p], *(const ull*)&nsy[2 * p],
                             *(const ull*)&nsz[2 * p], *(const ull*)&nsw[2 * p]);
            float2 dd = unpack2(d2p);
            if (a0) {
                if (pos < CAND)
                    mycand[pos] = ((ull)__float_as_uint(dd.x) << 32) | (unsigned)(2 * p);
                pos++;
            }
            if (a1) {
                if (pos < CAND)
                    mycand[pos] = ((ull)__float_as_uint(dd.y) << 32) | (unsigned)(2 * p + 1);
                pos++;
            }
        }
        __syncwarp();

        // ---- sort: 64-key fast path, 128-key fallback ----
        ull v[4];
        if (C <= 64) {
            #pragma unroll
            for (int qq = 0; qq < 2; qq++) {
                int e = qq * 32 + lane;
                v[qq] = (e < C) ? mycand[e] : ~0ull;
            }
            bitonic_sort<2>(v, lane);
        } else {
            #pragma unroll
            for (int qq = 0; qq < 4; qq++) {
                int e = qq * 32 + lane;
                v[qq] = (e < C) ? mycand[e] : ~0ull;
            }
            bitonic_sort<4>(v, lane);
        }

        // ---- edge output (coalesced) ----
        float* esrc = dout + ZOFF + (size_t)i * Kq;
        float* etgt = esrc + NKq;
        unsigned j0 = (unsigned)(v[0] & 0xffffffffu);
        unsigned j1 = (unsigned)(v[1] & 0xffffffffu);
        esrc[lane] = (float)(evM + (int)j0);
        if (lane < 8)  esrc[32 + lane] = (float)(evM + (int)j1);
        if (lane < 10) *(float4*)&etgt[4 * lane] =
            make_float4((float)i, (float)i, (float)i, (float)i);

        // ---- weight precompute: lane r holds rank r / r+32 ----
        float w0 = __expf(-10.f * __uint_as_float((unsigned)(v[0] >> 32)));
        float w1 = __expf(-10.f * __uint_as_float((unsigned)(v[1] >> 32)));

        // ---- top-40 broadcast aggregation (weights via shfl) ----
        float meanAcc = 0.f;
        float maxAcc  = __int_as_float(0xff800000);
        #pragma unroll 8
        for (int r = 0; r < Kq; r++) {
            unsigned jj = (r < 32) ? __shfl_sync(0xffffffffu, j0, r)
                                   : __shfl_sync(0xffffffffu, j1, r - 32);
            float wgt   = (r < 32) ? __shfl_sync(0xffffffffu, w0, r)
                                   : __shfl_sync(0xffffffffu, w1, r - 32);
            if (lane < PDQ) {
                float msg = hev[(size_t)jj * PDQ + lane] * wgt;
                meanAcc += msg;
                maxAcc = fmaxf(maxAcc, msg);
            }
        }
        if (lane < PDQ) {
            float* ag = g_aggr + (size_t)i * 2 * PDQ;
            ag[lane]       = meanAcc * (1.f / (float)Kq);
            ag[PDQ + lane] = maxAcc;
        }
        __syncwarp();
    }
}

// ================= row-tiled SIMT GEMM (R8 config: 8x8 f32x2, 2 CTAs) =====
template<int KD, int OC, int KCH, int NT, bool DOTANH, bool EVBIAS>
__global__ __launch_bounds__(NT, 2) void gemm_k(
    const float* __restrict__ A, const float* __restrict__ W,
    const float* __restrict__ bias, float* __restrict__ Cf)
{
    constexpr int RT = 128, AST = 132, CG = OC / 8;
    extern __shared__ float sm[];
    float* As  = sm;
    float* Wsm = sm + KCH * AST;
    int tid = threadIdx.x;
    int rowBase = blockIdx.x * RT;

    for (int idx = tid; idx < KD * OC / 4; idx += NT)
        ((float4*)Wsm)[idx] = ((const float4*)W)[idx];

    int cg = tid % CG, rg = tid / CG;
    int r0 = rg * 8, c0 = cg * 8;

    ull accp[4][8];
    {
        const float* bp = EVBIAS ? (bias + (rowBase >> 11) * 96) : bias;
        #pragma unroll
        for (int cc = 0; cc < 8; cc++) {
            ull bv = pack2(bp[c0 + cc], bp[c0 + cc]);
            #pragma unroll
            for (int rp = 0; rp < 4; rp++) accp[rp][cc] = bv;
        }
    }

    for (int kc = 0; kc < KD; kc += KCH) {
        __syncthreads();
        for (int idx = tid; idx < RT * KCH; idx += NT) {
            int r = idx / KCH, k = idx - r * KCH;
            As[k * AST + r] = A[(size_t)(rowBase + r) * KD + kc + k];
        }
        __syncthreads();
        #pragma unroll 8
        for (int k = 0; k < KCH; k++) {
            ulonglong2 a01 = *(const ulonglong2*)&As[k * AST + r0];
            ulonglong2 a23 = *(const ulonglong2*)&As[k * AST + r0 + 4];
            float4 w0 = *(const float4*)&Wsm[(kc + k) * OC + c0];
            float4 w1 = *(const float4*)&Wsm[(kc + k) * OC + c0 + 4];
            ull ap[4] = {a01.x, a01.y, a23.x, a23.y};
            ull wp[8] = {pack2(w0.x, w0.x), pack2(w0.y, w0.y),
                         pack2(w0.z, w0.z), pack2(w0.w, w0.w),
                         pack2(w1.x, w1.x), pack2(w1.y, w1.y),
                         pack2(w1.z, w1.z), pack2(w1.w, w1.w)};
            #pragma unroll
            for (int rp = 0; rp < 4; rp++)
                #pragma unroll
                for (int cc = 0; cc < 8; cc++)
                    accp[rp][cc] = fma2(ap[rp], wp[cc], accp[rp][cc]);
        }
    }

    #pragma unroll
    for (int rp = 0; rp < 4; rp++) {
        float vlo[8], vhi[8];
        #pragma unroll
        for (int cc = 0; cc < 8; cc++) {
            float2 f = unpack2(accp[rp][cc]);
            vlo[cc] = DOTANH ? fast_tanh(f.x) : f.x;
            vhi[cc] = DOTANH ? fast_tanh(f.y) : f.y;
        }
        size_t ro0 = (size_t)(rowBase + r0 + 2 * rp) * OC + c0;
        size_t ro1 = ro0 + OC;
        *(float4*)&Cf[ro0]     = make_float4(vlo[0], vlo[1], vlo[2], vlo[3]);
        *(float4*)&Cf[ro0 + 4] = make_float4(vlo[4], vlo[5], vlo[6], vlo[7]);
        *(float4*)&Cf[ro1]     = make_float4(vhi[0], vhi[1], vhi[2], vhi[3]);
        *(float4*)&Cf[ro1 + 4] = make_float4(vhi[4], vhi[5], vhi[6], vhi[7]);
    }
}

// ================= K2c fused: y = tanh(t@W2+b2) + per-chunk stats =========
// One block = 128 rows = one (event, chunk); writes g_y AND g_part.
__global__ __launch_bounds__(192, 2) void gemm_c_stats_k(
    const float* __restrict__ A, const float* __restrict__ W,
    const float* __restrict__ bias, float* __restrict__ Cf)
{
    constexpr int KD = 128, OC = 96, KCH = 64, NT = 192;
    constexpr int RT = 128, AST = 132, CG = 12;
    extern __shared__ float sm[];
    float* As  = sm;                    // KCH*AST (reused as red after mainloop)
    float* Wsm = sm + KCH * AST;
    int tid = threadIdx.x;
    int rowBase = blockIdx.x * RT;

    for (int idx = tid; idx < KD * OC / 4; idx += NT)
        ((float4*)Wsm)[idx] = ((const float4*)W)[idx];

    int cg = tid % CG, rg = tid / CG;
    int r0 = rg * 8, c0 = cg * 8;

    ull accp[4][8];
    #pragma unroll
    for (int cc = 0; cc < 8; cc++) {
        ull bv = pack2(bias[c0 + cc], bias[c0 + cc]);
        #pragma unroll
        for (int rp = 0; rp < 4; rp++) accp[rp][cc] = bv;
    }

    for (int kc = 0; kc < KD; kc += KCH) {
        __syncthreads();
        for (int idx = tid; idx < RT * KCH; idx += NT) {
            int r = idx / KCH, k = idx - r * KCH;
            As[k * AST + r] = A[(size_t)(rowBase + r) * KD + kc + k];
        }
        __syncthreads();
        #pragma unroll 8
        for (int k = 0; k < KCH; k++) {
            ulonglong2 a01 = *(const ulonglong2*)&As[k * AST + r0];
            ulonglong2 a23 = *(const ulonglong2*)&As[k * AST + r0 + 4];
            float4 w0 = *(const float4*)&Wsm[(kc + k) * OC + c0];
            float4 w1 = *(const float4*)&Wsm[(kc + k) * OC + c0 + 4];
            ull ap[4] = {a01.x, a01.y, a23.x, a23.y};
            ull wp[8] = {pack2(w0.x, w0.x), pack2(w0.y, w0.y),
                         pack2(w0.z, w0.z), pack2(w0.w, w0.w),
                         pack2(w1.x, w1.x), pack2(w1.y, w1.y),
                         pack2(w1.z, w1.z), pack2(w1.w, w1.w)};
            #pragma unroll
            for (int rp = 0; rp < 4; rp++)
                #pragma unroll
                for (int cc = 0; cc < 8; cc++)
                    accp[rp][cc] = fma2(ap[rp], wp[cc], accp[rp][cc]);
        }
    }

    // epilogue: tanh, store y, per-thread partial stats over its 8 rows
    float psum[8], pmin[8], pmax[8];
    #pragma unroll
    for (int cc = 0; cc < 8; cc++) {
        psum[cc] = 0.f;
        pmin[cc] = __int_as_float(0x7f800000);
        pmax[cc] = __int_as_float(0xff800000);
    }
    #pragma unroll
    for (int rp = 0; rp < 4; rp++) {
        float vlo[8], vhi[8];
        #pragma unroll
        for (int cc = 0; cc < 8; cc++) {
            float2 f = unpack2(accp[rp][cc]);
            vlo[cc] = fast_tanh(f.x);
            vhi[cc] = fast_tanh(f.y);
            psum[cc] += vlo[cc] + vhi[cc];
            pmin[cc] = fminf(pmin[cc], fminf(vlo[cc], vhi[cc]));
            pmax[cc] = fmaxf(pmax[cc], fmaxf(vlo[cc], vhi[cc]));
        }
        size_t ro0 = (size_t)(rowBase + r0 + 2 * rp) * OC + c0;
        size_t ro1 = ro0 + OC;
        *(float4*)&Cf[ro0]     = make_float4(vlo[0], vlo[1], vlo[2], vlo[3]);
        *(float4*)&Cf[ro0 + 4] = make_float4(vlo[4], vlo[5], vlo[6], vlo[7]);
        *(float4*)&Cf[ro1]     = make_float4(vhi[0], vhi[1], vhi[2], vhi[3]);
        *(float4*)&Cf[ro1 + 4] = make_float4(vhi[4], vhi[5], vhi[6], vhi[7]);
    }

    // block reduce over 16 row-groups (reuse As smem: 3*16*96 floats = 4608)
    float* red = As;
    __syncthreads();
    #pragma unroll
    for (int cc = 0; cc < 8; cc++) {
        red[(0 * 16 + rg) * 96 + c0 + cc] = psum[cc];
        red[(1 * 16 + rg) * 96 + c0 + cc] = pmin[cc];
        red[(2 * 16 + rg) * 96 + c0 + cc] = pmax[cc];
    }
    __syncthreads();
    if (tid < 96) {
        float s = 0.f, mn = __int_as_float(0x7f800000), mx = __int_as_float(0xff800000);
        #pragma unroll
        for (int g = 0; g < 16; g++) {
            s += red[(0 * 16 + g) * 96 + tid];
            mn = fminf(mn, red[(1 * 16 + g) * 96 + tid]);
            mx = fmaxf(mx, red[(2 * 16 + g) * 96 + tid]);
        }
        float* p = g_part + (size_t)blockIdx.x * 3 * 96;
        p[tid] = s; p[96 + tid] = mn; p[192 + tid] = mx;
    }
}

// ================= K2a: out = x@W_o1 + aggr@W_o2 + b_o2 (R8 config) =======
__global__ __launch_bounds__(192, 2) void gemm_out_k(
    const float* __restrict__ x, const float* __restrict__ aggr,
    const float* __restrict__ Wo1, const float* __restrict__ Wo2,
    const float* __restrict__ bias, float* __restrict__ outp)
{
    constexpr int RT = 128, AST = 132, NT = 192, OC = 96;
    extern __shared__ float sm[];
    float* As  = sm;                     // 48*132
    float* Ws1 = sm + 48 * AST;          // 96*96
    float* Ws2 = Ws1 + 96 * 96;          // 44*96
    int tid = threadIdx.x;
    int rowBase = blockIdx.x * RT;

    for (int idx = tid; idx < 96 * 96 / 4; idx += NT)
        ((float4*)Ws1)[idx] = ((const float4*)Wo1)[idx];
    for (int idx = tid; idx < 44 * 96 / 4; idx += NT)
        ((float4*)Ws2)[idx] = ((const float4*)Wo2)[idx];

    int cg = tid % 12, rg = tid / 12;
    int r0 = rg * 8, c0 = cg * 8;

    ull accp[4][8];
    #pragma unroll
    for (int cc = 0; cc < 8; cc++) {
        ull bv = pack2(bias[c0 + cc], bias[c0 + cc]);
        #pragma unroll
        for (int rp = 0; rp < 4; rp++) accp[rp][cc] = bv;
    }

    #pragma unroll
    for (int chunk = 0; chunk < 2; chunk++) {
        __syncthreads();
        for (int idx = tid; idx < RT * 48; idx += NT) {
            int r = idx / 48, k = idx - r * 48;
            As[k * AST + r] = x[(size_t)(rowBase + r) * 96 + chunk * 48 + k];
        }
        __syncthreads();
        #pragma unroll 8
        for (int k = 0; k < 48; k++) {
            ulonglong2 a01 = *(const ulonglong2*)&As[k * AST + r0];
            ulonglong2 a23 = *(const ulonglong2*)&As[k * AST + r0 + 4];
            float4 w0 = *(const float4*)&Ws1[(chunk * 48 + k) * OC + c0];
            float4 w1 = *(const float4*)&Ws1[(chunk * 48 + k) * OC + c0 + 4];
            ull ap[4] = {a01.x, a01.y, a23.x, a23.y};
            ull wp[8] = {pack2(w0.x, w0.x), pack2(w0.y, w0.y),
                         pack2(w0.z, w0.z), pack2(w0.w, w0.w),
                         pack2(w1.x, w1.x), pack2(w1.y, w1.y),
                         pack2(w1.z, w1.z), pack2(w1.w, w1.w)};
            #pragma unroll
            for (int rp = 0; rp < 4; rp++)
                #pragma unroll
                for (int cc = 0; cc < 8; cc++)
                    accp[rp][cc] = fma2(ap[rp], wp[cc], accp[rp][cc]);
        }
    }
    __syncthreads();
    for (int idx = tid; idx < RT * 44; idx += NT) {
        int r = idx / 44, k = idx - r * 44;
        As[k * AST + r] = aggr[(size_t)(rowBase + r) * 44 + k];
    }
    __syncthreads();
    #pragma unroll 4
    for (int k = 0; k < 44; k++) {
        ulonglong2 a01 = *(const ulonglong2*)&As[k * AST + r0];
        ulonglong2 a23 = *(const ulonglong2*)&As[k * AST + r0 + 4];
        float4 w0 = *(const float4*)&Ws2[k * OC + c0];
        float4 w1 = *(const float4*)&Ws2[k * OC + c0 + 4];
        ull ap[4] = {a01.x, a01.y, a23.x, a23.y};
        ull wp[8] = {pack2(w0.x, w0.x), pack2(w0.y, w0.y),
                     pack2(w0.z, w0.z), pack2(w0.w, w0.w),
                     pack2(w1.x, w1.x), pack2(w1.y, w1.y),
                     pack2(w1.z, w1.z), pack2(w1.w, w1.w)};
        #pragma unroll
        for (int rp = 0; rp < 4; rp++)
            #pragma unroll
            for (int cc = 0; cc < 8; cc++)
                accp[rp][cc] = fma2(ap[rp], wp[cc], accp[rp][cc]);
    }

    #pragma unroll
    for (int rp = 0; rp < 4; rp++) {
        float vlo[8], vhi[8];
        #pragma unroll
        for (int cc = 0; cc < 8; cc++) {
            float2 f = unpack2(accp[rp][cc]);
            vlo[cc] = f.x; vhi[cc] = f.y;
        }
        size_t ro0 = (size_t)(rowBase + r0 + 2 * rp) * OC + c0;
        size_t ro1 = ro0 + OC;
        *(float4*)&outp[ro0]     = make_float4(vlo[0], vlo[1], vlo[2], vlo[3]);
        *(float4*)&outp[ro0 + 4] = make_float4(vlo[4], vlo[5], vlo[6], vlo[7]);
        *(float4*)&outp[ro1]     = make_float4(vhi[0], vhi[1], vhi[2], vhi[3]);
        *(float4*)&outp[ro1 + 4] = make_float4(vhi[4], vhi[5], vhi[6], vhi[7]);
    }
}

// ================= K3b: reduce partials + stats@W3[0:288]+b3 =============
__global__ __launch_bounds__(96) void stats2_k(
    const float* __restrict__ W3, const float* __restrict__ b3)
{
    int ev = blockIdx.x, tid = threadIdx.x;
    __shared__ float st[288];

    float sm = 0.f, mn = __int_as_float(0x7f800000), mx = __int_as_float(0xff800000);
    for (int ch = 0; ch < 16; ch++) {
        const float* p = g_part + ((size_t)(ev * 16 + ch) * 3) * 96;
        sm += p[tid];
        mn = fminf(mn, p[96 + tid]);
        mx = fmaxf(mx, p[192 + tid]);
    }
    st[tid]       = sm * (1.f / (float)Mq);
    st[96 + tid]  = mn;
    st[192 + tid] = mx;
    __syncthreads();

    float acc = b3[tid];
    #pragma unroll 4
    for (int k = 0; k < 288; k++) acc = fmaf(st[k], W3[(size_t)k * 96 + tid], acc);
    g_c3[ev * 96 + tid] = acc;
}

// ================= host launcher =========================================
extern "C" void kernel_launch(void* const* d_in, const int* in_sizes, int n_in,
                              void* d_out, int out_size)
{
    (void)out_size;
    static const int EXPECTED[15] = {
        3145728, 32768, 384, 4, 2112, 22, 9216, 4224, 96, 12288, 128, 12288, 96, 36864, 96
    };
    const void* P[15];
    bool ok = (n_in >= 15);
    if (ok) for (int i = 0; i < 15; i++) if (in_sizes[i] != EXPECTED[i]) { ok = false; break; }
    if (ok) {
        for (int i = 0; i < 15; i++) P[i] = d_in[i];
    } else {
        bool used[64] = {false};
        for (int r = 0; r < 15; r++) {
            P[r] = nullptr;
            for (int j = 0; j < n_in && j < 64; j++) {
                if (!used[j] && in_sizes[j] == EXPECTED[r]) { P[r] = d_in[j]; used[j] = true; break; }
            }
        }
    }

    const float* x   = (const float*)P[0];
    const float* Ws  = (const float*)P[2];
    const float* bs  = (const float*)P[3];
    const float* Wh  = (const float*)P[4];
    const float* bh  = (const float*)P[5];
    const float* Wo1 = (const float*)P[6];
    const float* Wo2 = (const float*)P[7];
    const float* bo2 = (const float*)P[8];
    const float* W1  = (const float*)P[9];
    const float* b1  = (const float*)P[10];
    const float* W2  = (const float*)P[11];
    const float* b2  = (const float*)P[12];
    const float* W3  = (const float*)P[13];
    const float* b3  = (const float*)P[14];
    float* dout = (float*)d_out;

    float *p_aggr, *p_out, *p_t, *p_y, *p_c3;
    cudaGetSymbolAddress((void**)&p_aggr, g_aggr);
    cudaGetSymbolAddress((void**)&p_out,  g_out);
    cudaGetSymbolAddress((void**)&p_t,    g_t);
    cudaGetSymbolAddress((void**)&p_y,    g_y);
    cudaGetSymbolAddress((void**)&p_c3,   g_c3);

    const int SMEM_KNN = 8192 * 4 + 8 * 1024 * 4 + 8 * CAND * 8;   // 73728
    const int SMEM_OUT = (48 * 132 + 96 * 96 + 44 * 96) * 4;       // 79104
    const int SMEM_B   = (96 * 132 + 96 * 128) * 4;                // 99840
    const int SMEM_C   = (64 * 132 + 128 * 96) * 4;                // 82944
    const int SMEM_Z   = (96 * 132 + 96 * 96) * 4;                 // 87552
    cudaFuncSetAttribute(knn_kernel, cudaFuncAttributeMaxDynamicSharedMemorySize, SMEM_KNN);
    cudaFuncSetAttribute(gemm_out_k, cudaFuncAttributeMaxDynamicSharedMemorySize, SMEM_OUT);
    cudaFuncSetAttribute(gemm_k<96, 128, 96, 256, true, false>,
                         cudaFuncAttributeMaxDynamicSharedMemorySize, SMEM_B);
    cudaFuncSetAttribute(gemm_c_stats_k,
                         cudaFuncAttributeMaxDynamicSharedMemorySize, SMEM_C);
    cudaFuncSetAttribute(gemm_k<96, 96, 96, 192, true, true>,
                         cudaFuncAttributeMaxDynamicSharedMemorySize, SMEM_Z);

    sh_kernel<<<Nq / 32, 256>>>(x, Ws, bs, Wh, bh);
    knn_kernel<<<Nq / 16, 256, SMEM_KNN>>>(dout);
    gemm_out_k<<<Nq / 128, 192, SMEM_OUT>>>(x, p_aggr, Wo1, Wo2, bo2, p_out);
    gemm_k<96, 128, 96, 256, true, false><<<Nq / 128, 256, SMEM_B>>>(p_out, W1, b1, p_t);
    gemm_c_stats_k<<<Nq / 128, 192, SMEM_C>>>(p_t, W2, b2, p_y);
    stats2_k<<<Bq, 96>>>(W3, b3);
    gemm_k<96, 96, 96, 192, true, true><<<Nq / 128, 192, SMEM_Z>>>(p_y, W3 + 288 * 96, p_c3, dout);
}

// round 17
// speedup vs baseline: 1.9217x; 1.0809x over previous
#include <cuda_runtime.h>
#include <cstdint>

// ---------------- problem constants ----------------
#define Bq   16
#define Mq   2048
#define Kq   40
#define Nq   (Bq*Mq)      // 32768
#define INC  96
#define SDQ  4
#define PDQ  22
#define H1   128
#define CAND 128

typedef unsigned long long ull;

static const size_t ZOFF = (size_t)Nq * 96;        // floats before edge_index
static const size_t NKq  = (size_t)Nq * Kq;

// ---------------- device scratch ----------------
__device__ float g_s[Nq * SDQ];
__device__ float g_h[Nq * PDQ];
__device__ float g_aggr[Nq * 2 * PDQ];
__device__ float g_out[Nq * 96];
__device__ float g_t[Nq * H1];
__device__ float g_y[Nq * 96];
__device__ float g_c3[Bq * 96];
__device__ float g_part[Bq * 16 * 3 * 96];

__device__ __forceinline__ float fast_tanh(float v) {
    float e = __expf(2.f * v);
    return (e - 1.f) * __frcp_rn(e + 1.f);
}

// ---------------- packed f32x2 helpers (sm_103a) ----------------
__device__ __forceinline__ ull pack2(float a, float b) {
    ull r; asm("mov.b64 %0, {%1,%2};" : "=l"(r) : "f"(a), "f"(b)); return r;
}
__device__ __forceinline__ float2 unpack2(ull v) {
    float2 f; asm("mov.b64 {%0,%1}, %2;" : "=f"(f.x), "=f"(f.y) : "l"(v)); return f;
}
__device__ __forceinline__ ull fma2(ull a, ull b, ull c) {
    ull d; asm("fma.rn.f32x2 %0, %1, %2, %3;" : "=l"(d) : "l"(a), "l"(b), "l"(c)); return d;
}
__device__ __forceinline__ ull add2(ull a, ull b) {
    ull d; asm("add.rn.f32x2 %0, %1, %2;" : "=l"(d) : "l"(a), "l"(b)); return d;
}
__device__ __forceinline__ ull mul2(ull a, ull b) {
    ull d; asm("mul.rn.f32x2 %0, %1, %2;" : "=l"(d) : "l"(a), "l"(b)); return d;
}

// packed pair distance over NEGATED neighbor coords: per-element IEEE-rn ops
// in the SAME order as the scalar d2exact chain -> bit-identical results.
__device__ __forceinline__ ull d2pair(ull sqx2, ull sqy2, ull sqz2, ull sqw2,
                                      ull nx, ull ny, ull nz, ull nw) {
    ull px = add2(sqx2, nx), py = add2(sqy2, ny);
    ull pz = add2(sqz2, nz), pw = add2(sqw2, nw);
    return fma2(px, px, fma2(py, py, fma2(pz, pz, mul2(pw, pw))));
}

// ---- bitonic sort of NR*32 u64 keys, ascending (warp-collective) ----
template<int NR>
__device__ __forceinline__ void bitonic_sort(ull* v, int lane)
{
    #pragma unroll
    for (int kk = 2; kk <= NR * 32; kk <<= 1) {
        #pragma unroll
        for (int j = kk >> 1; j > 0; j >>= 1) {
            if (j >= 32) {
                int qx = j >> 5;
                #pragma unroll
                for (int q = 0; q < NR; q++) {
                    if ((q & qx) == 0) {
                        int e = q * 32 + lane;
                        bool up = ((e & kk) == 0);
                        ull a = v[q], b = v[q | qx];
                        bool sw2 = up ? (a > b) : (a < b);
                        if (sw2) { v[q] = b; v[q | qx] = a; }
                    }
                }
            } else {
                #pragma unroll
                for (int q = 0; q < NR; q++) {
                    int e = q * 32 + lane;
                    bool up = ((e & kk) == 0);
                    ull o = __shfl_xor_sync(0xffffffffu, v[q], j);
                    bool keepmin = (((lane & j) == 0) == up);
                    bool take = keepmin ? (o < v[q]) : (o > v[q]);
                    if (take) v[q] = o;
                }
            }
        }
    }
}

// ================= K0: s = x@W_s + b_s ; h = x@W_h + b_h =================
__global__ __launch_bounds__(256) void sh_kernel(
    const float* __restrict__ x,
    const float* __restrict__ Ws, const float* __restrict__ bs,
    const float* __restrict__ Wh, const float* __restrict__ bh)
{
    __shared__ float wsh[INC * 26];
    __shared__ float xs[32][INC];
    int tid = threadIdx.x;
    for (int idx = tid; idx < INC * 26; idx += 256) {
        int k = idx / 26, od = idx % 26;
        wsh[idx] = (od < SDQ) ? Ws[k * SDQ + od] : Wh[k * PDQ + (od - SDQ)];
    }
    const float* xb = x + (size_t)blockIdx.x * 32 * INC;
    for (int idx = tid; idx < 32 * INC / 4; idx += 256)
        ((float4*)xs)[idx] = ((const float4*)xb)[idx];
    __syncthreads();

    int w = tid >> 5, od = tid & 31;
    if (od < 26) {
        float bv = (od < SDQ) ? bs[od] : bh[od - SDQ];
        #pragma unroll
        for (int q = 0; q < 4; q++) {
            int nl = w * 4 + q;
            float acc = 0.f;
            #pragma unroll 8
            for (int k = 0; k < INC; k++) acc = fmaf(xs[nl][k], wsh[k * 26 + od], acc);
            int n = blockIdx.x * 32 + nl;
            if (od < SDQ) g_s[n * SDQ + od] = acc + bv;
            else          g_h[n * PDQ + (od - SDQ)] = acc + bv;
        }
    }
}

// ================= K1: kNN + weighted mean/max aggregation + edges =======
// 512 threads (16 warps) share one event tile; 2 queries/warp; 2 CTAs/SM ->
// 32 warps/SM for latency hiding. Inner machinery identical to R16.
__global__ __launch_bounds__(512, 2) void knn_kernel(float* __restrict__ dout)
{
    extern __shared__ float dsm[];
    float* nsx = dsm;                 // 2048 (negated coords)
    float* nsy = dsm + 2048;
    float* nsz = dsm + 4096;
    float* nsw = dsm + 6144;
    unsigned* d16 = (unsigned*)(dsm + 8192);          // 16 warps * 1024 u32 (64KB)
    ull* cand = (ull*)(dsm + 8192 + 16 * 1024);       // 16 * 128 u64 (16KB)

    int tid  = threadIdx.x;
    int lane = tid & 31;
    int w    = tid >> 5;
    int ev     = blockIdx.x >> 6;                // 64 blocks / event
    int qbase0 = (blockIdx.x & 63) * 32;

    const float4* sev = (const float4*)(g_s + (size_t)ev * Mq * SDQ);
    for (int j = tid; j < Mq; j += 512) {
        float4 s = sev[j];
        nsx[j] = -s.x; nsy[j] = -s.y; nsz[j] = -s.z; nsw[j] = -s.w;
    }
    __syncthreads();

    unsigned* myd16 = d16 + w * 1024;
    ull* mycand = cand + w * CAND;
    const uint4* dv16 = (const uint4*)myd16;
    const float* hev = g_h + (size_t)ev * Mq * PDQ;
    int evM = ev * Mq;
    float Twarm = -1.f;

    for (int q = 0; q < 2; q++) {
        int qloc = qbase0 + w * 2 + q;
        int i = evM + qloc;
        float sqx = -nsx[qloc], sqy = -nsy[qloc], sqz = -nsz[qloc], sqw = -nsw[qloc];
        ull sqx2 = pack2(sqx, sqx), sqy2 = pack2(sqy, sqy);
        ull sqz2 = pack2(sqz, sqz), sqw2 = pack2(sqw, sqw);

        // ---- distance pass: packed f32x2; fsum only for first query ----
        float T;
        if (Twarm > 0.f) {
            #pragma unroll 8
            for (int t = 0; t < 32; t++) {
                int p = lane + 32 * t;
                ull d2p = d2pair(sqx2, sqy2, sqz2, sqw2,
                                 *(const ull*)&nsx[2 * p], *(const ull*)&nsy[2 * p],
                                 *(const ull*)&nsz[2 * p], *(const ull*)&nsw[2 * p]);
                float2 dd = unpack2(d2p);
                myd16[p] = (__float_as_uint(dd.x) >> 16) | (__float_as_uint(dd.y) & 0xffff0000u);
            }
            T = Twarm;
        } else {
            ull fs2 = pack2(0.f, 0.f);
            #pragma unroll 8
            for (int t = 0; t < 32; t++) {
                int p = lane + 32 * t;
                ull d2p = d2pair(sqx2, sqy2, sqz2, sqw2,
                                 *(const ull*)&nsx[2 * p], *(const ull*)&nsy[2 * p],
                                 *(const ull*)&nsz[2 * p], *(const ull*)&nsw[2 * p]);
                float2 dd = unpack2(d2p);
                myd16[p] = (__float_as_uint(dd.x) >> 16) | (__float_as_uint(dd.y) & 0xffff0000u);
                fs2 = add2(fs2, d2p);
            }
            float2 fsp = unpack2(fs2);
            float fsum = fsp.x + fsp.y;
            #pragma unroll
            for (int o = 16; o; o >>= 1) fsum += __shfl_xor_sync(0xffffffffu, fsum, o);
            T = fsum * (0.20f / 2048.f);
        }
        __syncwarp();

        // ---- threshold search: vectorized probes; count in [Kq, 64] ----
        float lo = 0.f, hi = 3.3e38f;
        unsigned T16 = 0u;
        bool found = false;
        for (int it = 0; it < 16 && !found; ++it) {
            T16 = __float_as_uint(T) >> 16;
            unsigned TT = T16 * 0x10001u;
            unsigned acc = 0;
            #pragma unroll
            for (int t4 = 0; t4 < 8; t4++) {
                uint4 u = dv16[lane + 32 * t4];
                acc = __vadd2(acc, __vsetleu2(u.x, TT));
                acc = __vadd2(acc, __vsetleu2(u.y, TT));
                acc = __vadd2(acc, __vsetleu2(u.z, TT));
                acc = __vadd2(acc, __vsetleu2(u.w, TT));
            }
            int c = (int)((acc & 0xffffu) + (acc >> 16));
            c = __reduce_add_sync(0xffffffffu, c);
            if (c >= Kq && c <= 64) { found = true; break; }
            if (c < Kq) {
                lo = T;
                float Tm = T * sqrtf(50.f / fmaxf((float)c, 2.f));
                if (hi < 3e38f) {
                    float wdt = hi - lo;
                    Tm = fminf(fmaxf(Tm, lo + 0.25f * wdt), lo + 0.75f * wdt);
                } else {
                    Tm = fmaxf(Tm, T * 1.5f);
                }
                T = Tm;
            } else {
                hi = T;
                float Tm = T * sqrtf(50.f / (float)c);
                float wdt = hi - lo;
                Tm = fminf(fmaxf(Tm, lo + 0.25f * wdt), lo + 0.75f * wdt);
                T = Tm;
            }
        }
        if (!found) {   // exact bisection in u16 space (guaranteed >= Kq)
            unsigned l = 0u, h = 0x7f80u;
            for (int it = 0; it < 18 && !found; ++it) {
                unsigned mid = l + ((h - l) >> 1);
                unsigned TT = mid * 0x10001u;
                unsigned acc = 0;
                #pragma unroll
                for (int t4 = 0; t4 < 8; t4++) {
                    uint4 u = dv16[lane + 32 * t4];
                    acc = __vadd2(acc, __vsetleu2(u.x, TT));
                    acc = __vadd2(acc, __vsetleu2(u.y, TT));
                    acc = __vadd2(acc, __vsetleu2(u.z, TT));
                    acc = __vadd2(acc, __vsetleu2(u.w, TT));
                }
                int cc = (int)((acc & 0xffffu) + (acc >> 16));
                cc = __reduce_add_sync(0xffffffffu, cc);
                if (cc >= Kq && cc <= 64) { T16 = mid; found = true; }
                else if (cc >= Kq) h = mid;
                else l = mid;
                if (!found && h - l <= 1u) { T16 = h; found = true; }
            }
        }
        Twarm = __uint_as_float((T16 << 16) | 0xffffu);

        // ---- re-count in per-lane layout; build accept-slot mask ----
        unsigned TT = T16 * 0x10001u;
        unsigned accv = 0u, tmask = 0u;
        #pragma unroll
        for (int t = 0; t < 32; t++) {
            unsigned r2 = __vsetleu2(myd16[lane + 32 * t], TT);
            accv = __vadd2(accv, r2);
            if (r2) tmask |= (1u << t);
        }
        int cnt = (int)((accv & 0xffffu) + (accv >> 16));
        int incl = cnt;
        #pragma unroll
        for (int d = 1; d < 32; d <<= 1) {
            int n = __shfl_up_sync(0xffffffffu, incl, d);
            if (lane >= d) incl += n;
        }
        int pos = incl - cnt;                        // exclusive offset
        int C = __shfl_sync(0xffffffffu, incl, 31);  // total accepted
        if (C > CAND) C = CAND;

        // ---- sparse walk over accept slots only ----
        while (tmask) {
            int t = __ffs(tmask) - 1;
            tmask &= tmask - 1u;
            int p = lane + 32 * t;
            unsigned u = myd16[p];
            bool a0 = (u & 0xffffu) <= T16;
            bool a1 = (u >> 16) <= T16;
            ull d2p = d2pair(sqx2, sqy2, sqz2, sqw2,
                             *(const ull*)&nsx[2 * p], *(const ull*)&nsy[2 * p],
                             *(const ull*)&nsz[2 * p], *(const ull*)&nsw[2 * p]);
            float2 dd = unpack2(d2p);
            if (a0) {
                if (pos < CAND)
                    mycand[pos] = ((ull)__float_as_uint(dd.x) << 32) | (unsigned)(2 * p);
                pos++;
            }
            if (a1) {
                if (pos < CAND)
                    mycand[pos] = ((ull)__float_as_uint(dd.y) << 32) | (unsigned)(2 * p + 1);
                pos++;
            }
        }
        __syncwarp();

        // ---- sort: 64-key fast path, 128-key fallback ----
        ull v[4];
        if (C <= 64) {
            #pragma unroll
            for (int qq = 0; qq < 2; qq++) {
                int e = qq * 32 + lane;
                v[qq] = (e < C) ? mycand[e] : ~0ull;
            }
            bitonic_sort<2>(v, lane);
        } else {
            #pragma unroll
            for (int qq = 0; qq < 4; qq++) {
                int e = qq * 32 + lane;
                v[qq] = (e < C) ? mycand[e] : ~0ull;
            }
            bitonic_sort<4>(v, lane);
        }

        // ---- edge output (coalesced) ----
        float* esrc = dout + ZOFF + (size_t)i * Kq;
        float* etgt = esrc + NKq;
        unsigned j0 = (unsigned)(v[0] & 0xffffffffu);
        unsigned j1 = (unsigned)(v[1] & 0xffffffffu);
        esrc[lane] = (float)(evM + (int)j0);
        if (lane < 8)  esrc[32 + lane] = (float)(evM + (int)j1);
        if (lane < 10) *(float4*)&etgt[4 * lane] =
            make_float4((float)i, (float)i, (float)i, (float)i);

        // ---- weight precompute: lane r holds rank r / r+32 ----
        float w0 = __expf(-10.f * __uint_as_float((unsigned)(v[0] >> 32)));
        float w1 = __expf(-10.f * __uint_as_float((unsigned)(v[1] >> 32)));

        // ---- top-40 broadcast aggregation (weights via shfl) ----
        float meanAcc = 0.f;
        float maxAcc  = __int_as_float(0xff800000);
        #pragma unroll 8
        for (int r = 0; r < Kq; r++) {
            unsigned jj = (r < 32) ? __shfl_sync(0xffffffffu, j0, r)
                                   : __shfl_sync(0xffffffffu, j1, r - 32);
            float wgt   = (r < 32) ? __shfl_sync(0xffffffffu, w0, r)
                                   : __shfl_sync(0xffffffffu, w1, r - 32);
            if (lane < PDQ) {
                float msg = hev[(size_t)jj * PDQ + lane] * wgt;
                meanAcc += msg;
                maxAcc = fmaxf(maxAcc, msg);
            }
        }
        if (lane < PDQ) {
            float* ag = g_aggr + (size_t)i * 2 * PDQ;
            ag[lane]       = meanAcc * (1.f / (float)Kq);
            ag[PDQ + lane] = maxAcc;
        }
        __syncwarp();
    }
}

// ================= row-tiled SIMT GEMM (R8 config: 8x8 f32x2, 2 CTAs) =====
template<int KD, int OC, int KCH, int NT, bool DOTANH, bool EVBIAS>
__global__ __launch_bounds__(NT, 2) void gemm_k(
    const float* __restrict__ A, const float* __restrict__ W,
    const float* __restrict__ bias, float* __restrict__ Cf)
{
    constexpr int RT = 128, AST = 132, CG = OC / 8;
    extern __shared__ float sm[];
    float* As  = sm;
    float* Wsm = sm + KCH * AST;
    int tid = threadIdx.x;
    int rowBase = blockIdx.x * RT;

    for (int idx = tid; idx < KD * OC / 4; idx += NT)
        ((float4*)Wsm)[idx] = ((const float4*)W)[idx];

    int cg = tid % CG, rg = tid / CG;
    int r0 = rg * 8, c0 = cg * 8;

    ull accp[4][8];
    {
        const float* bp = EVBIAS ? (bias + (rowBase >> 11) * 96) : bias;
        #pragma unroll
        for (int cc = 0; cc < 8; cc++) {
            ull bv = pack2(bp[c0 + cc], bp[c0 + cc]);
            #pragma unroll
            for (int rp = 0; rp < 4; rp++) accp[rp][cc] = bv;
        }
    }

    for (int kc = 0; kc < KD; kc += KCH) {
        __syncthreads();
        for (int idx = tid; idx < RT * KCH; idx += NT) {
            int r = idx / KCH, k = idx - r * KCH;
            As[k * AST + r] = A[(size_t)(rowBase + r) * KD + kc + k];
        }
        __syncthreads();
        #pragma unroll 8
        for (int k = 0; k < KCH; k++) {
            ulonglong2 a01 = *(const ulonglong2*)&As[k * AST + r0];
            ulonglong2 a23 = *(const ulonglong2*)&As[k * AST + r0 + 4];
            float4 w0 = *(const float4*)&Wsm[(kc + k) * OC + c0];
            float4 w1 = *(const float4*)&Wsm[(kc + k) * OC + c0 + 4];
            ull ap[4] = {a01.x, a01.y, a23.x, a23.y};
            ull wp[8] = {pack2(w0.x, w0.x), pack2(w0.y, w0.y),
                         pack2(w0.z, w0.z), pack2(w0.w, w0.w),
                         pack2(w1.x, w1.x), pack2(w1.y, w1.y),
                         pack2(w1.z, w1.z), pack2(w1.w, w1.w)};
            #pragma unroll
            for (int rp = 0; rp < 4; rp++)
                #pragma unroll
                for (int cc = 0; cc < 8; cc++)
                    accp[rp][cc] = fma2(ap[rp], wp[cc], accp[rp][cc]);
        }
    }

    #pragma unroll
    for (int rp = 0; rp < 4; rp++) {
        float vlo[8], vhi[8];
        #pragma unroll
        for (int cc = 0; cc < 8; cc++) {
            float2 f = unpack2(accp[rp][cc]);
            vlo[cc] = DOTANH ? fast_tanh(f.x) : f.x;
            vhi[cc] = DOTANH ? fast_tanh(f.y) : f.y;
        }
        size_t ro0 = (size_t)(rowBase + r0 + 2 * rp) * OC + c0;
        size_t ro1 = ro0 + OC;
        *(float4*)&Cf[ro0]     = make_float4(vlo[0], vlo[1], vlo[2], vlo[3]);
        *(float4*)&Cf[ro0 + 4] = make_float4(vlo[4], vlo[5], vlo[6], vlo[7]);
        *(float4*)&Cf[ro1]     = make_float4(vhi[0], vhi[1], vhi[2], vhi[3]);
        *(float4*)&Cf[ro1 + 4] = make_float4(vhi[4], vhi[5], vhi[6], vhi[7]);
    }
}

// ================= K2c fused: y = tanh(t@W2+b2) + per-chunk stats =========
__global__ __launch_bounds__(192, 2) void gemm_c_stats_k(
    const float* __restrict__ A, const float* __restrict__ W,
    const float* __restrict__ bias, float* __restrict__ Cf)
{
    constexpr int KD = 128, OC = 96, KCH = 64, NT = 192;
    constexpr int RT = 128, AST = 132, CG = 12;
    extern __shared__ float sm[];
    float* As  = sm;                    // KCH*AST (reused as red after mainloop)
    float* Wsm = sm + KCH * AST;
    int tid = threadIdx.x;
    int rowBase = blockIdx.x * RT;

    for (int idx = tid; idx < KD * OC / 4; idx += NT)
        ((float4*)Wsm)[idx] = ((const float4*)W)[idx];

    int cg = tid % CG, rg = tid / CG;
    int r0 = rg * 8, c0 = cg * 8;

    ull accp[4][8];
    #pragma unroll
    for (int cc = 0; cc < 8; cc++) {
        ull bv = pack2(bias[c0 + cc], bias[c0 + cc]);
        #pragma unroll
        for (int rp = 0; rp < 4; rp++) accp[rp][cc] = bv;
    }

    for (int kc = 0; kc < KD; kc += KCH) {
        __syncthreads();
        for (int idx = tid; idx < RT * KCH; idx += NT) {
            int r = idx / KCH, k = idx - r * KCH;
            As[k * AST + r] = A[(size_t)(rowBase + r) * KD + kc + k];
        }
        __syncthreads();
        #pragma unroll 8
        for (int k = 0; k < KCH; k++) {
            ulonglong2 a01 = *(const ulonglong2*)&As[k * AST + r0];
            ulonglong2 a23 = *(const ulonglong2*)&As[k * AST + r0 + 4];
            float4 w0 = *(const float4*)&Wsm[(kc + k) * OC + c0];
            float4 w1 = *(const float4*)&Wsm[(kc + k) * OC + c0 + 4];
            ull ap[4] = {a01.x, a01.y, a23.x, a23.y};
            ull wp[8] = {pack2(w0.x, w0.x), pack2(w0.y, w0.y),
                         pack2(w0.z, w0.z), pack2(w0.w, w0.w),
                         pack2(w1.x, w1.x), pack2(w1.y, w1.y),
                         pack2(w1.z, w1.z), pack2(w1.w, w1.w)};
            #pragma unroll
            for (int rp = 0; rp < 4; rp++)
                #pragma unroll
                for (int cc = 0; cc < 8; cc++)
                    accp[rp][cc] = fma2(ap[rp], wp[cc], accp[rp][cc]);
        }
    }

    float psum[8], pmin[8], pmax[8];
    #pragma unroll
    for (int cc = 0; cc < 8; cc++) {
        psum[cc] = 0.f;
        pmin[cc] = __int_as_float(0x7f800000);
        pmax[cc] = __int_as_float(0xff800000);
    }
    #pragma unroll
    for (int rp = 0; rp < 4; rp++) {
        float vlo[8], vhi[8];
        #pragma unroll
        for (int cc = 0; cc < 8; cc++) {
            float2 f = unpack2(accp[rp][cc]);
            vlo[cc] = fast_tanh(f.x);
            vhi[cc] = fast_tanh(f.y);
            psum[cc] += vlo[cc] + vhi[cc];
            pmin[cc] = fminf(pmin[cc], fminf(vlo[cc], vhi[cc]));
            pmax[cc] = fmaxf(pmax[cc], fmaxf(vlo[cc], vhi[cc]));
        }
        size_t ro0 = (size_t)(rowBase + r0 + 2 * rp) * OC + c0;
        size_t ro1 = ro0 + OC;
        *(float4*)&Cf[ro0]     = make_float4(vlo[0], vlo[1], vlo[2], vlo[3]);
        *(float4*)&Cf[ro0 + 4] = make_float4(vlo[4], vlo[5], vlo[6], vlo[7]);
        *(float4*)&Cf[ro1]     = make_float4(vhi[0], vhi[1], vhi[2], vhi[3]);
        *(float4*)&Cf[ro1 + 4] = make_float4(vhi[4], vhi[5], vhi[6], vhi[7]);
    }

    float* red = As;
    __syncthreads();
    #pragma unroll
    for (int cc = 0; cc < 8; cc++) {
        red[(0 * 16 + rg) * 96 + c0 + cc] = psum[cc];
        red[(1 * 16 + rg) * 96 + c0 + cc] = pmin[cc];
        red[(2 * 16 + rg) * 96 + c0 + cc] = pmax[cc];
    }
    __syncthreads();
    if (tid < 96) {
        float s = 0.f, mn = __int_as_float(0x7f800000), mx = __int_as_float(0xff800000);
        #pragma unroll
        for (int g = 0; g < 16; g++) {
            s += red[(0 * 16 + g) * 96 + tid];
            mn = fminf(mn, red[(1 * 16 + g) * 96 + tid]);
            mx = fmaxf(mx, red[(2 * 16 + g) * 96 + tid]);
        }
        float* p = g_part + (size_t)blockIdx.x * 3 * 96;
        p[tid] = s; p[96 + tid] = mn; p[192 + tid] = mx;
    }
}

// ================= K2a: out = x@W_o1 + aggr@W_o2 + b_o2 (R8 config) =======
__global__ __launch_bounds__(192, 2) void gemm_out_k(
    const float* __restrict__ x, const float* __restrict__ aggr,
    const float* __restrict__ Wo1, const float* __restrict__ Wo2,
    const float* __restrict__ bias, float* __restrict__ outp)
{
    constexpr int RT = 128, AST = 132, NT = 192, OC = 96;
    extern __shared__ float sm[];
    float* As  = sm;                     // 48*132
    float* Ws1 = sm + 48 * AST;          // 96*96
    float* Ws2 = Ws1 + 96 * 96;          // 44*96
    int tid = threadIdx.x;
    int rowBase = blockIdx.x * RT;

    for (int idx = tid; idx < 96 * 96 / 4; idx += NT)
        ((float4*)Ws1)[idx] = ((const float4*)Wo1)[idx];
    for (int idx = tid; idx < 44 * 96 / 4; idx += NT)
        ((float4*)Ws2)[idx] = ((const float4*)Wo2)[idx];

    int cg = tid % 12, rg = tid / 12;
    int r0 = rg * 8, c0 = cg * 8;

    ull accp[4][8];
    #pragma unroll
    for (int cc = 0; cc < 8; cc++) {
        ull bv = pack2(bias[c0 + cc], bias[c0 + cc]);
        #pragma unroll
        for (int rp = 0; rp < 4; rp++) accp[rp][cc] = bv;
    }

    #pragma unroll
    for (int chunk = 0; chunk < 2; chunk++) {
        __syncthreads();
        for (int idx = tid; idx < RT * 48; idx += NT) {
            int r = idx / 48, k = idx - r * 48;
            As[k * AST + r] = x[(size_t)(rowBase + r) * 96 + chunk * 48 + k];
        }
        __syncthreads();
        #pragma unroll 8
        for (int k = 0; k < 48; k++) {
            ulonglong2 a01 = *(const ulonglong2*)&As[k * AST + r0];
            ulonglong2 a23 = *(const ulonglong2*)&As[k * AST + r0 + 4];
            float4 w0 = *(const float4*)&Ws1[(chunk * 48 + k) * OC + c0];
            float4 w1 = *(const float4*)&Ws1[(chunk * 48 + k) * OC + c0 + 4];
            ull ap[4] = {a01.x, a01.y, a23.x, a23.y};
            ull wp[8] = {pack2(w0.x, w0.x), pack2(w0.y, w0.y),
                         pack2(w0.z, w0.z), pack2(w0.w, w0.w),
                         pack2(w1.x, w1.x), pack2(w1.y, w1.y),
                         pack2(w1.z, w1.z), pack2(w1.w, w1.w)};
            #pragma unroll
            for (int rp = 0; rp < 4; rp++)
                #pragma unroll
                for (int cc = 0; cc < 8; cc++)
                    accp[rp][cc] = fma2(ap[rp], wp[cc], accp[rp][cc]);
        }
    }
    __syncthreads();
    for (int idx = tid; idx < RT * 44; idx += NT) {
        int r = idx / 44, k = idx - r * 44;
        As[k * AST + r] = aggr[(size_t)(rowBase + r) * 44 + k];
    }
    __syncthreads();
    #pragma unroll 4
    for (int k = 0; k < 44; k++) {
        ulonglong2 a01 = *(const ulonglong2*)&As[k * AST + r0];
        ulonglong2 a23 = *(const ulonglong2*)&As[k * AST + r0 + 4];
        float4 w0 = *(const float4*)&Ws2[k * OC + c0];
        float4 w1 = *(const float4*)&Ws2[k * OC + c0 + 4];
        ull ap[4] = {a01.x, a01.y, a23.x, a23.y};
        ull wp[8] = {pack2(w0.x, w0.x), pack2(w0.y, w0.y),
                     pack2(w0.z, w0.z), pack2(w0.w, w0.w),
                     pack2(w1.x, w1.x), pack2(w1.y, w1.y),
                     pack2(w1.z, w1.z), pack2(w1.w, w1.w)};
        #pragma unroll
        for (int rp = 0; rp < 4; rp++)
            #pragma unroll
            for (int cc = 0; cc < 8; cc++)
                accp[rp][cc] = fma2(ap[rp], wp[cc], accp[rp][cc]);
    }

    #pragma unroll
    for (int rp = 0; rp < 4; rp++) {
        float vlo[8], vhi[8];
        #pragma unroll
        for (int cc = 0; cc < 8; cc++) {
            float2 f = unpack2(accp[rp][cc]);
            vlo[cc] = f.x; vhi[cc] = f.y;
        }
        size_t ro0 = (size_t)(rowBase + r0 + 2 * rp) * OC + c0;
        size_t ro1 = ro0 + OC;
        *(float4*)&outp[ro0]     = make_float4(vlo[0], vlo[1], vlo[2], vlo[3]);
        *(float4*)&outp[ro0 + 4] = make_float4(vlo[4], vlo[5], vlo[6], vlo[7]);
        *(float4*)&outp[ro1]     = make_float4(vhi[0], vhi[1], vhi[2], vhi[3]);
        *(float4*)&outp[ro1 + 4] = make_float4(vhi[4], vhi[5], vhi[6], vhi[7]);
    }
}

// ================= K3b: reduce partials + stats@W3[0:288]+b3 =============
__global__ __launch_bounds__(96) void stats2_k(
    const float* __restrict__ W3, const float* __restrict__ b3)
{
    int ev = blockIdx.x, tid = threadIdx.x;
    __shared__ float st[288];

    float sm = 0.f, mn = __int_as_float(0x7f800000), mx = __int_as_float(0xff800000);
    for (int ch = 0; ch < 16; ch++) {
        const float* p = g_part + ((size_t)(ev * 16 + ch) * 3) * 96;
        sm += p[tid];
        mn = fminf(mn, p[96 + tid]);
        mx = fmaxf(mx, p[192 + tid]);
    }
    st[tid]       = sm * (1.f / (float)Mq);
    st[96 + tid]  = mn;
    st[192 + tid] = mx;
    __syncthreads();

    float acc = b3[tid];
    #pragma unroll 4
    for (int k = 0; k < 288; k++) acc = fmaf(st[k], W3[(size_t)k * 96 + tid], acc);
    g_c3[ev * 96 + tid] = acc;
}

// ================= host launcher =========================================
extern "C" void kernel_launch(void* const* d_in, const int* in_sizes, int n_in,
                              void* d_out, int out_size)
{
    (void)out_size;
    static const int EXPECTED[15] = {
        3145728, 32768, 384, 4, 2112, 22, 9216, 4224, 96, 12288, 128, 12288, 96, 36864, 96
    };
    const void* P[15];
    bool ok = (n_in >= 15);
    if (ok) for (int i = 0; i < 15; i++) if (in_sizes[i] != EXPECTED[i]) { ok = false; break; }
    if (ok) {
        for (int i = 0; i < 15; i++) P[i] = d_in[i];
    } else {
        bool used[64] = {false};
        for (int r = 0; r < 15; r++) {
            P[r] = nullptr;
            for (int j = 0; j < n_in && j < 64; j++) {
                if (!used[j] && in_sizes[j] == EXPECTED[r]) { P[r] = d_in[j]; used[j] = true; break; }
            }
        }
    }

    const float* x   = (const float*)P[0];
    const float* Ws  = (const float*)P[2];
    const float* bs  = (const float*)P[3];
    const float* Wh  = (const float*)P[4];
    const float* bh  = (const float*)P[5];
    const float* Wo1 = (const float*)P[6];
    const float* Wo2 = (const float*)P[7];
    const float* bo2 = (const float*)P[8];
    const float* W1  = (const float*)P[9];
    const float* b1  = (const float*)P[10];
    const float* W2  = (const float*)P[11];
    const float* b2  = (const float*)P[12];
    const float* W3  = (const float*)P[13];
    const float* b3  = (const float*)P[14];
    float* dout = (float*)d_out;

    float *p_aggr, *p_out, *p_t, *p_y, *p_c3;
    cudaGetSymbolAddress((void**)&p_aggr, g_aggr);
    cudaGetSymbolAddress((void**)&p_out,  g_out);
    cudaGetSymbolAddress((void**)&p_t,    g_t);
    cudaGetSymbolAddress((void**)&p_y,    g_y);
    cudaGetSymbolAddress((void**)&p_c3,   g_c3);

    const int SMEM_KNN = 8192 * 4 + 16 * 1024 * 4 + 16 * CAND * 8;  // 114688
    const int SMEM_OUT = (48 * 132 + 96 * 96 + 44 * 96) * 4;        // 79104
    const int SMEM_B   = (96 * 132 + 96 * 128) * 4;                 // 99840
    const int SMEM_C   = (64 * 132 + 128 * 96) * 4;                 // 82944
    const int SMEM_Z   = (96 * 132 + 96 * 96) * 4;                  // 87552
    cudaFuncSetAttribute(knn_kernel, cudaFuncAttributeMaxDynamicSharedMemorySize, SMEM_KNN);
    cudaFuncSetAttribute(gemm_out_k, cudaFuncAttributeMaxDynamicSharedMemorySize, SMEM_OUT);
    cudaFuncSetAttribute(gemm_k<96, 128, 96, 256, true, false>,
                         cudaFuncAttributeMaxDynamicSharedMemorySize, SMEM_B);
    cudaFuncSetAttribute(gemm_c_stats_k,
                         cudaFuncAttributeMaxDynamicSharedMemorySize, SMEM_C);
    cudaFuncSetAttribute(gemm_k<96, 96, 96, 192, true, true>,
                         cudaFuncAttributeMaxDynamicSharedMemorySize, SMEM_Z);

    sh_kernel<<<Nq / 32, 256>>>(x, Ws, bs, Wh, bh);
    knn_kernel<<<Nq / 32, 512, SMEM_KNN>>>(dout);
    gemm_out_k<<<Nq / 128, 192, SMEM_OUT>>>(x, p_aggr, Wo1, Wo2, bo2, p_out);
    gemm_k<96, 128, 96, 256, true, false><<<Nq / 128, 256, SMEM_B>>>(p_out, W1, b1, p_t);
    gemm_c_stats_k<<<Nq / 128, 192, SMEM_C>>>(p_t, W2, b2, p_y);
    stats2_k<<<Bq, 96>>>(W3, b3);
    gemm_k<96, 96, 96, 192, true, true><<<Nq / 128, 192, SMEM_Z>>>(p_y, W3 + 288 * 96, p_c3, dout);
}